// round 2
// baseline (speedup 1.0000x reference)
#include <cuda_runtime.h>
#include <math.h>

// Problem constants
#define BB 8
#define SS 1024
#define DD 512
#define HH 8
#define HD 64
#define S2 (SS/2)

// ---------------- scratch (static device globals; no cudaMalloc) -------------
__device__ float g_qkv   [(size_t)BB*SS*3*DD];      // 12.6M  (reused for both MHAs)
__device__ float g_scores[(size_t)BB*HH*SS*SS];     // 67.1M  (reused)
__device__ float g_attn  [(size_t)BB*SS*DD];        // 4.2M   (attn output, reused)
__device__ float g_x1    [(size_t)BB*SS*DD];
__device__ float g_pooled[(size_t)BB*S2*DD];
__device__ float g_a2    [(size_t)BB*S2*DD];
__device__ float g_x2    [(size_t)BB*SS*DD];
__device__ float g_h     [(size_t)BB*SS*4*DD];      // 16.8M
__device__ float g_ff    [(size_t)BB*SS*DD];

// ---------------- dense GEMM: C[M,N] = A[M,K] @ W[N,K]^T + bias --------------
// 128x128 tile, BK=8, 256 threads, 8x8 microtile. M,N mult of 128; K mult of 8.
template<int GELU>
__global__ __launch_bounds__(256, 2)
void gemm_nt(const float* __restrict__ A, const float* __restrict__ W,
             const float* __restrict__ bias, float* __restrict__ C,
             int M, int N, int K)
{
    __shared__ float As[8][128];
    __shared__ float Bs[8][128];
    const int tid = threadIdx.x;
    const int lr = tid >> 1;          // 0..127
    const int lc = (tid & 1) << 2;    // 0 or 4
    const int tx = tid & 15;
    const int ty = tid >> 4;

    const float* Ap = A + (size_t)(blockIdx.y * 128 + lr) * K + lc;
    const float* Wp = W + (size_t)(blockIdx.x * 128 + lr) * K + lc;

    float acc[8][8];
#pragma unroll
    for (int i = 0; i < 8; i++)
#pragma unroll
        for (int j = 0; j < 8; j++) acc[i][j] = 0.f;

    for (int k0 = 0; k0 < K; k0 += 8) {
        float4 a4 = *(const float4*)(Ap + k0);
        float4 b4 = *(const float4*)(Wp + k0);
        __syncthreads();
        As[lc + 0][lr] = a4.x; As[lc + 1][lr] = a4.y;
        As[lc + 2][lr] = a4.z; As[lc + 3][lr] = a4.w;
        Bs[lc + 0][lr] = b4.x; Bs[lc + 1][lr] = b4.y;
        Bs[lc + 2][lr] = b4.z; Bs[lc + 3][lr] = b4.w;
        __syncthreads();
#pragma unroll
        for (int k = 0; k < 8; k++) {
            float ar[8], br[8];
            *(float4*)(ar)     = *(const float4*)&As[k][ty * 8];
            *(float4*)(ar + 4) = *(const float4*)&As[k][ty * 8 + 4];
            *(float4*)(br)     = *(const float4*)&Bs[k][tx * 8];
            *(float4*)(br + 4) = *(const float4*)&Bs[k][tx * 8 + 4];
#pragma unroll
            for (int i = 0; i < 8; i++)
#pragma unroll
                for (int j = 0; j < 8; j++)
                    acc[i][j] = fmaf(ar[i], br[j], acc[i][j]);
        }
    }

    const int n0 = blockIdx.x * 128 + tx * 8;
#pragma unroll
    for (int i = 0; i < 8; i++) {
        size_t row = (size_t)blockIdx.y * 128 + ty * 8 + i;
        float* Cp = C + row * N + n0;
#pragma unroll
        for (int j = 0; j < 8; j++) {
            float v = acc[i][j] + bias[n0 + j];
            if (GELU) v = 0.5f * v * (1.0f + erff(v * 0.70710678118654752f));
            Cp[j] = v;
        }
    }
}

// ---------------- scores = (Q K^T) * 0.125  (batched over B*H) ---------------
// qkv layout: [b, s, 3*D] with q@0, k@D, v@2D; each [H,HD]. 64x64x16 tiles.
__global__ __launch_bounds__(256)
void qk_gemm(const float* __restrict__ qkv, float* __restrict__ scores, int Sseq)
{
    const int z = blockIdx.z;
    const int b = z >> 3, h = z & 7;
    const float* Qb = qkv + (size_t)b * Sseq * (3 * DD) + h * HD;
    const float* Kb = Qb + DD;
    float* Cb = scores + (size_t)z * Sseq * Sseq;

    __shared__ float As[16][64];
    __shared__ float Bs[16][64];
    const int tid = threadIdx.x;
    const int lr = tid >> 2;          // 0..63
    const int lc = (tid & 3) << 2;    // 0,4,8,12
    const int tx = tid & 15, ty = tid >> 4;

    const float* Ap = Qb + (size_t)(blockIdx.y * 64 + lr) * (3 * DD) + lc;
    const float* Bp = Kb + (size_t)(blockIdx.x * 64 + lr) * (3 * DD) + lc;

    float acc[4][4] = {};
    for (int k0 = 0; k0 < HD; k0 += 16) {
        float4 a4 = *(const float4*)(Ap + k0);
        float4 b4 = *(const float4*)(Bp + k0);
        __syncthreads();
        As[lc + 0][lr] = a4.x; As[lc + 1][lr] = a4.y;
        As[lc + 2][lr] = a4.z; As[lc + 3][lr] = a4.w;
        Bs[lc + 0][lr] = b4.x; Bs[lc + 1][lr] = b4.y;
        Bs[lc + 2][lr] = b4.z; Bs[lc + 3][lr] = b4.w;
        __syncthreads();
#pragma unroll
        for (int k = 0; k < 16; k++) {
            float4 ar = *(const float4*)&As[k][ty * 4];
            float4 br = *(const float4*)&Bs[k][tx * 4];
            float a[4] = {ar.x, ar.y, ar.z, ar.w};
            float bv[4] = {br.x, br.y, br.z, br.w};
#pragma unroll
            for (int i = 0; i < 4; i++)
#pragma unroll
                for (int j = 0; j < 4; j++)
                    acc[i][j] = fmaf(a[i], bv[j], acc[i][j]);
        }
    }
#pragma unroll
    for (int i = 0; i < 4; i++) {
        size_t row = (size_t)(blockIdx.y * 64 + ty * 4 + i);
#pragma unroll
        for (int j = 0; j < 4; j++)
            Cb[row * Sseq + blockIdx.x * 64 + tx * 4 + j] = acc[i][j] * 0.125f;
    }
}

// ---------------- O = P @ V  (batched, N=HD=64) ------------------------------
__global__ __launch_bounds__(256)
void av_gemm(const float* __restrict__ scores, const float* __restrict__ qkv,
             float* __restrict__ out, int Sseq)
{
    const int z = blockIdx.z;
    const int b = z >> 3, h = z & 7;
    const float* P = scores + (size_t)z * Sseq * Sseq;
    const float* V = qkv + (size_t)b * Sseq * (3 * DD) + 2 * DD + h * HD;
    float* O = out + (size_t)b * Sseq * DD + h * HD;

    __shared__ float As[16][64];
    __shared__ float Bs[16][64];
    const int tid = threadIdx.x;
    const int ar_ = tid >> 2, ac = (tid & 3) << 2;   // A: 64 rows x 16 k
    const int br_ = tid >> 4, bc = (tid & 15) << 2;  // B: 16 k x 64 n
    const int tx = tid & 15, ty = tid >> 4;
    const int m0 = blockIdx.y * 64;

    float acc[4][4] = {};
    for (int k0 = 0; k0 < Sseq; k0 += 16) {
        float4 a4 = *(const float4*)(P + (size_t)(m0 + ar_) * Sseq + k0 + ac);
        float4 b4 = *(const float4*)(V + (size_t)(k0 + br_) * (3 * DD) + bc);
        __syncthreads();
        As[ac + 0][ar_] = a4.x; As[ac + 1][ar_] = a4.y;
        As[ac + 2][ar_] = a4.z; As[ac + 3][ar_] = a4.w;
        *(float4*)&Bs[br_][bc] = b4;
        __syncthreads();
#pragma unroll
        for (int k = 0; k < 16; k++) {
            float4 ar4 = *(const float4*)&As[k][ty * 4];
            float4 br4 = *(const float4*)&Bs[k][tx * 4];
            float a[4] = {ar4.x, ar4.y, ar4.z, ar4.w};
            float bv[4] = {br4.x, br4.y, br4.z, br4.w};
#pragma unroll
            for (int i = 0; i < 4; i++)
#pragma unroll
                for (int j = 0; j < 4; j++)
                    acc[i][j] = fmaf(a[i], bv[j], acc[i][j]);
        }
    }
#pragma unroll
    for (int i = 0; i < 4; i++)
#pragma unroll
        for (int j = 0; j < 4; j++)
            O[(size_t)(m0 + ty * 4 + i) * DD + tx * 4 + j] = acc[i][j];
}

// ---------------- row softmax (in place) -------------------------------------
__global__ void softmax_k(float* __restrict__ s, int len)
{
    float* p = s + (size_t)blockIdx.x * len;
    const int tid = threadIdx.x;
    __shared__ float sh[8];

    float mx = -1e30f;
    for (int i = tid; i < len; i += 256) mx = fmaxf(mx, p[i]);
#pragma unroll
    for (int o = 16; o; o >>= 1) mx = fmaxf(mx, __shfl_xor_sync(~0u, mx, o));
    if ((tid & 31) == 0) sh[tid >> 5] = mx;
    __syncthreads();
    if (tid < 8) {
        float v = sh[tid];
#pragma unroll
        for (int o = 4; o; o >>= 1) v = fmaxf(v, __shfl_xor_sync(0xff, v, o));
        if (tid == 0) sh[0] = v;
    }
    __syncthreads();
    mx = sh[0];
    __syncthreads();

    float sum = 0.f;
    for (int i = tid; i < len; i += 256) {
        float e = __expf(p[i] - mx);
        p[i] = e;
        sum += e;
    }
#pragma unroll
    for (int o = 16; o; o >>= 1) sum += __shfl_xor_sync(~0u, sum, o);
    if ((tid & 31) == 0) sh[tid >> 5] = sum;
    __syncthreads();
    if (tid < 8) {
        float v = sh[tid];
#pragma unroll
        for (int o = 4; o; o >>= 1) v += __shfl_xor_sync(0xff, v, o);
        if (tid == 0) sh[0] = v;
    }
    __syncthreads();
    float inv = 1.0f / sh[0];
    for (int i = tid; i < len; i += 256) p[i] *= inv;
}

// ---------------- LN(a + b) over D=512; 128 threads/row ----------------------
__device__ __forceinline__ void ln_finish(float v[4], int tid, const float* g,
                                          const float* be, float* outp)
{
    float s1 = v[0] + v[1] + v[2] + v[3];
    float s2 = v[0] * v[0] + v[1] * v[1] + v[2] * v[2] + v[3] * v[3];
#pragma unroll
    for (int o = 16; o; o >>= 1) {
        s1 += __shfl_xor_sync(~0u, s1, o);
        s2 += __shfl_xor_sync(~0u, s2, o);
    }
    __shared__ float sh1[4], sh2[4];
    if ((tid & 31) == 0) { sh1[tid >> 5] = s1; sh2[tid >> 5] = s2; }
    __syncthreads();
    float rs1 = sh1[0] + sh1[1] + sh1[2] + sh1[3];
    float rs2 = sh2[0] + sh2[1] + sh2[2] + sh2[3];
    float mean = rs1 * (1.0f / 512.0f);
    float var = rs2 * (1.0f / 512.0f) - mean * mean;
    float rstd = rsqrtf(var + 1e-5f);
    float4 g4 = *(const float4*)(g + tid * 4);
    float4 b4 = *(const float4*)(be + tid * 4);
    float4 o4;
    o4.x = (v[0] - mean) * rstd * g4.x + b4.x;
    o4.y = (v[1] - mean) * rstd * g4.y + b4.y;
    o4.z = (v[2] - mean) * rstd * g4.z + b4.z;
    o4.w = (v[3] - mean) * rstd * g4.w + b4.w;
    *(float4*)outp = o4;
}

__global__ __launch_bounds__(128)
void ln_add_k(const float* __restrict__ a, const float* __restrict__ bsrc,
              const float* __restrict__ g, const float* __restrict__ be,
              float* __restrict__ out)
{
    const size_t base = (size_t)blockIdx.x * DD;
    const int tid = threadIdx.x;
    float4 va = *(const float4*)(a + base + tid * 4);
    float4 vb = *(const float4*)(bsrc + base + tid * 4);
    float v[4] = {va.x + vb.x, va.y + vb.y, va.z + vb.z, va.w + vb.w};
    ln_finish(v, tid, g, be, out + base + tid * 4);
}

// LN( x1 + linear_interp_upsample(a2) )
__global__ __launch_bounds__(128)
void ln_interp_k(const float* __restrict__ x1, const float* __restrict__ a2,
                 const float* __restrict__ g, const float* __restrict__ be,
                 float* __restrict__ out)
{
    const int r = blockIdx.x;
    const int b = r >> 10, i = r & 1023;
    float src = (i + 0.5f) * 0.5f - 0.5f;
    src = fminf(fmaxf(src, 0.0f), (float)(S2 - 1));
    int i0 = (int)floorf(src);
    int i1 = min(i0 + 1, S2 - 1);
    float w = src - (float)i0;

    const size_t base = (size_t)r * DD;
    const size_t b0 = ((size_t)b * S2 + i0) * DD;
    const size_t b1 = ((size_t)b * S2 + i1) * DD;
    const int tid = threadIdx.x;

    float4 vx = *(const float4*)(x1 + base + tid * 4);
    float4 v0 = *(const float4*)(a2 + b0 + tid * 4);
    float4 v1 = *(const float4*)(a2 + b1 + tid * 4);
    float v[4];
    v[0] = vx.x + v0.x * (1.f - w) + v1.x * w;
    v[1] = vx.y + v0.y * (1.f - w) + v1.y * w;
    v[2] = vx.z + v0.z * (1.f - w) + v1.z * w;
    v[3] = vx.w + v0.w * (1.f - w) + v1.w * w;
    ln_finish(v, tid, g, be, out + base + tid * 4);
}

// avg_pool1d k=2 s=2
__global__ void pool_k(const float* __restrict__ x, float* __restrict__ out)
{
    size_t idx = (size_t)blockIdx.x * 256 + threadIdx.x; // B*S2*D total
    int d = (int)(idx & 511);
    size_t bt = idx >> 9;
    int t = (int)(bt & (S2 - 1));
    int b = (int)(bt >> 9);
    size_t src = ((size_t)b * SS + 2 * t) * DD + d;
    out[idx] = 0.5f * (x[src] + x[src + DD]);
}

// ---------------- host side ---------------------------------------------------
extern "C" void kernel_launch(void* const* d_in, const int* in_sizes, int n_in,
                              void* d_out, int out_size)
{
    const float* x      = (const float*)d_in[0];
    const float* w_in1  = (const float*)d_in[1];
    const float* b_in1  = (const float*)d_in[2];
    const float* w_out1 = (const float*)d_in[3];
    const float* b_out1 = (const float*)d_in[4];
    const float* w_in2  = (const float*)d_in[5];
    const float* b_in2  = (const float*)d_in[6];
    const float* w_out2 = (const float*)d_in[7];
    const float* b_out2 = (const float*)d_in[8];
    const float* g1     = (const float*)d_in[9];
    const float* beta1  = (const float*)d_in[10];
    const float* g2     = (const float*)d_in[11];
    const float* beta2  = (const float*)d_in[12];
    const float* g3     = (const float*)d_in[13];
    const float* beta3  = (const float*)d_in[14];
    const float* w_ff1  = (const float*)d_in[15];
    const float* b_ff1  = (const float*)d_in[16];
    const float* w_ff2  = (const float*)d_in[17];
    const float* b_ff2  = (const float*)d_in[18];

    float *qkv, *scores, *attn, *x1, *pooled, *a2, *x2, *h, *ff;
    cudaGetSymbolAddress((void**)&qkv,    g_qkv);
    cudaGetSymbolAddress((void**)&scores, g_scores);
    cudaGetSymbolAddress((void**)&attn,   g_attn);
    cudaGetSymbolAddress((void**)&x1,     g_x1);
    cudaGetSymbolAddress((void**)&pooled, g_pooled);
    cudaGetSymbolAddress((void**)&a2,     g_a2);
    cudaGetSymbolAddress((void**)&x2,     g_x2);
    cudaGetSymbolAddress((void**)&h,      g_h);
    cudaGetSymbolAddress((void**)&ff,     g_ff);

    const int M1 = BB * SS;   // 8192
    const int M2 = BB * S2;   // 4096

    // ---- MHA 1 ----
    gemm_nt<0><<<dim3(1536 / 128, M1 / 128), 256>>>(x, w_in1, b_in1, qkv, M1, 1536, 512);
    qk_gemm<<<dim3(SS / 64, SS / 64, BB * HH), 256>>>(qkv, scores, SS);
    softmax_k<<<BB * HH * SS, 256>>>(scores, SS);
    av_gemm<<<dim3(1, SS / 64, BB * HH), 256>>>(scores, qkv, attn, SS);
    gemm_nt<0><<<dim3(512 / 128, M1 / 128), 256>>>(attn, w_out1, b_out1, ff, M1, 512, 512);
    ln_add_k<<<M1, 128>>>(x, ff, g1, beta1, x1);

    // ---- pool + MHA 2 ----
    pool_k<<<(BB * S2 * DD) / 256, 256>>>(x1, pooled);
    gemm_nt<0><<<dim3(1536 / 128, M2 / 128), 256>>>(pooled, w_in2, b_in2, qkv, M2, 1536, 512);
    qk_gemm<<<dim3(S2 / 64, S2 / 64, BB * HH), 256>>>(qkv, scores, S2);
    softmax_k<<<BB * HH * S2, 256>>>(scores, S2);
    av_gemm<<<dim3(1, S2 / 64, BB * HH), 256>>>(scores, qkv, attn, S2);
    gemm_nt<0><<<dim3(512 / 128, M2 / 128), 256>>>(attn, w_out2, b_out2, a2, M2, 512, 512);

    // ---- upsample + residual + LN2 ----
    ln_interp_k<<<M1, 128>>>(x1, a2, g2, beta2, x2);

    // ---- FFN ----
    gemm_nt<1><<<dim3(2048 / 128, M1 / 128), 256>>>(x2, w_ff1, b_ff1, h, M1, 2048, 512);
    gemm_nt<0><<<dim3(512 / 128, M1 / 128), 256>>>(h, w_ff2, b_ff2, ff, M1, 512, 2048);
    ln_add_k<<<M1, 128>>>(x2, ff, g3, beta3, (float*)d_out);
}

// round 3
// speedup vs baseline: 1.5549x; 1.5549x over previous
#include <cuda_runtime.h>
#include <mma.h>
#include <math.h>

using namespace nvcuda;

// Problem constants
#define BB 8
#define SS 1024
#define DD 512
#define HH 8
#define HD 64
#define S2 (SS/2)

#define BKPAD 24   // BK=16 + 8 pad (ldm must be mult of 8)

// ---------------- scratch (static device globals; no cudaMalloc) -------------
__device__ float g_qkv   [(size_t)BB*SS*3*DD];
__device__ float g_scores[(size_t)BB*HH*SS*SS];
__device__ float g_attn  [(size_t)BB*SS*DD];
__device__ float g_x1    [(size_t)BB*SS*DD];
__device__ float g_pooled[(size_t)BB*S2*DD];
__device__ float g_a2    [(size_t)BB*S2*DD];
__device__ float g_x2    [(size_t)BB*SS*DD];
__device__ float g_h     [(size_t)BB*SS*4*DD];
__device__ float g_ff    [(size_t)BB*SS*DD];

// =====================================================================
// Batched tf32 WMMA GEMM.
//   TRANS_B=1 (NT): C[m,n] = sum_k A[m,k] * B[n,k]   (B row-major [N,K])
//   TRANS_B=0 (NN): C[m,n] = sum_k A[m,k] * B[k,n]   (B row-major [K,N])
// Batch index z -> (b = z>>3, h = z&7); per-matrix strides for b and h.
// All of M, N divisible by BM, BN; K divisible by 16; lds divisible by 4.
// =====================================================================
template<int BM, int BN, int TM, int TN, int TRANS_B>
__global__ __launch_bounds__(32*(BM/(TM*16))*(BN/(TN*16)))
void gemm_wmma(const float* __restrict__ A, int ldA, long sAb, long sAh,
               const float* __restrict__ B, int ldB, long sBb, long sBh,
               float* __restrict__ C, int ldC, long sCb, long sCh,
               int K, float scale)
{
    constexpr int WARPS_M = BM / (TM * 16);
    constexpr int WARPS_N = BN / (TN * 16);
    constexpr int NTH = WARPS_M * WARPS_N * 32;
    constexpr int BK = 16;
    constexpr int BNPAD = BN + 8;
    constexpr int BSZ = TRANS_B ? BN * BKPAD : BK * BNPAD;

    const int z = blockIdx.z;
    const int bb = z >> 3, hh = z & 7;
    A += (size_t)bb * sAb + (size_t)hh * sAh;
    B += (size_t)bb * sBb + (size_t)hh * sBh;
    C += (size_t)bb * sCb + (size_t)hh * sCh;

    __shared__ float As[BM * BKPAD];
    __shared__ float Bs[BSZ];

    const int tid = threadIdx.x;
    const int wid = tid >> 5;
    const int warp_m = wid % WARPS_M;
    const int warp_n = wid / WARPS_M;
    const int m0 = blockIdx.y * BM;
    const int n0 = blockIdx.x * BN;

    wmma::fragment<wmma::accumulator, 16, 16, 8, float> acc[TM][TN];
#pragma unroll
    for (int i = 0; i < TM; i++)
#pragma unroll
        for (int j = 0; j < TN; j++) wmma::fill_fragment(acc[i][j], 0.0f);

    for (int k0 = 0; k0 < K; k0 += BK) {
        __syncthreads();
        // load A tile [BM x BK]
#pragma unroll
        for (int i = tid; i < BM * BK / 4; i += NTH) {
            int r = i / (BK / 4);
            int c = (i % (BK / 4)) * 4;
            float4 v = *(const float4*)(A + (size_t)(m0 + r) * ldA + k0 + c);
            *(float4*)&As[r * BKPAD + c] = v;
        }
        if (TRANS_B) {
            // B tile [BN rows(n) x BK cols(k)]
#pragma unroll
            for (int i = tid; i < BN * BK / 4; i += NTH) {
                int r = i / (BK / 4);
                int c = (i % (BK / 4)) * 4;
                float4 v = *(const float4*)(B + (size_t)(n0 + r) * ldB + k0 + c);
                *(float4*)&Bs[r * BKPAD + c] = v;
            }
        } else {
            // B tile [BK rows(k) x BN cols(n)]
#pragma unroll
            for (int i = tid; i < BK * BN / 4; i += NTH) {
                int r = i / (BN / 4);
                int c = (i % (BN / 4)) * 4;
                float4 v = *(const float4*)(B + (size_t)(k0 + r) * ldB + n0 + c);
                *(float4*)&Bs[r * BNPAD + c] = v;
            }
        }
        __syncthreads();

#pragma unroll
        for (int ks = 0; ks < 2; ks++) {
            const int kk = ks * 8;
            wmma::fragment<wmma::matrix_a, 16, 16, 8, wmma::precision::tf32,
                           wmma::row_major> af[TM];
#pragma unroll
            for (int i = 0; i < TM; i++) {
                wmma::load_matrix_sync(af[i],
                    &As[(warp_m * TM * 16 + i * 16) * BKPAD + kk], BKPAD);
#pragma unroll
                for (int t = 0; t < af[i].num_elements; t++)
                    af[i].x[t] = wmma::__float_to_tf32(af[i].x[t]);
            }
            if (TRANS_B) {
                wmma::fragment<wmma::matrix_b, 16, 16, 8, wmma::precision::tf32,
                               wmma::col_major> bf[TN];
#pragma unroll
                for (int j = 0; j < TN; j++) {
                    wmma::load_matrix_sync(bf[j],
                        &Bs[(warp_n * TN * 16 + j * 16) * BKPAD + kk], BKPAD);
#pragma unroll
                    for (int t = 0; t < bf[j].num_elements; t++)
                        bf[j].x[t] = wmma::__float_to_tf32(bf[j].x[t]);
                }
#pragma unroll
                for (int i = 0; i < TM; i++)
#pragma unroll
                    for (int j = 0; j < TN; j++)
                        wmma::mma_sync(acc[i][j], af[i], bf[j], acc[i][j]);
            } else {
                wmma::fragment<wmma::matrix_b, 16, 16, 8, wmma::precision::tf32,
                               wmma::row_major> bf[TN];
#pragma unroll
                for (int j = 0; j < TN; j++) {
                    wmma::load_matrix_sync(bf[j],
                        &Bs[kk * BNPAD + warp_n * TN * 16 + j * 16], BNPAD);
#pragma unroll
                    for (int t = 0; t < bf[j].num_elements; t++)
                        bf[j].x[t] = wmma::__float_to_tf32(bf[j].x[t]);
                }
#pragma unroll
                for (int i = 0; i < TM; i++)
#pragma unroll
                    for (int j = 0; j < TN; j++)
                        wmma::mma_sync(acc[i][j], af[i], bf[j], acc[i][j]);
            }
        }
    }

#pragma unroll
    for (int i = 0; i < TM; i++)
#pragma unroll
        for (int j = 0; j < TN; j++) {
#pragma unroll
            for (int t = 0; t < acc[i][j].num_elements; t++)
                acc[i][j].x[t] *= scale;
            wmma::store_matrix_sync(
                C + (size_t)(m0 + warp_m * TM * 16 + i * 16) * ldC
                  + n0 + warp_n * TN * 16 + j * 16,
                acc[i][j], ldC, wmma::mem_row_major);
        }
}

// ---------------- elementwise bias (+ optional exact GELU) -------------------
template<int GELU>
__global__ void bias_act_k(float* __restrict__ t, const float* __restrict__ bias,
                           int ncols4)
{
    size_t i4 = (size_t)blockIdx.x * blockDim.x + threadIdx.x;
    float4 v = ((float4*)t)[i4];
    int col4 = (int)(i4 % ncols4);
    float4 bv = ((const float4*)bias)[col4];
    v.x += bv.x; v.y += bv.y; v.z += bv.z; v.w += bv.w;
    if (GELU) {
        v.x = 0.5f * v.x * (1.0f + erff(v.x * 0.70710678118654752f));
        v.y = 0.5f * v.y * (1.0f + erff(v.y * 0.70710678118654752f));
        v.z = 0.5f * v.z * (1.0f + erff(v.z * 0.70710678118654752f));
        v.w = 0.5f * v.w * (1.0f + erff(v.w * 0.70710678118654752f));
    }
    ((float4*)t)[i4] = v;
}

// ---------------- register-resident row softmax (one load, one store) --------
// block = len/4 threads (256 or 128), one float4 per thread
__global__ void softmax_fast(float* __restrict__ s)
{
    float* p = s + (size_t)blockIdx.x * (blockDim.x * 4);
    const int tid = threadIdx.x;
    const int wid = tid >> 5, lane = tid & 31;
    const int nw = blockDim.x >> 5;
    __shared__ float sh[8];

    float4 v = *(float4*)(p + tid * 4);
    float mx = fmaxf(fmaxf(v.x, v.y), fmaxf(v.z, v.w));
#pragma unroll
    for (int o = 16; o; o >>= 1) mx = fmaxf(mx, __shfl_xor_sync(~0u, mx, o));
    if (lane == 0) sh[wid] = mx;
    __syncthreads();
    mx = sh[0];
    for (int i = 1; i < nw; i++) mx = fmaxf(mx, sh[i]);
    __syncthreads();

    v.x = __expf(v.x - mx); v.y = __expf(v.y - mx);
    v.z = __expf(v.z - mx); v.w = __expf(v.w - mx);
    float sum = v.x + v.y + v.z + v.w;
#pragma unroll
    for (int o = 16; o; o >>= 1) sum += __shfl_xor_sync(~0u, sum, o);
    if (lane == 0) sh[wid] = sum;
    __syncthreads();
    float tot = 0.f;
    for (int i = 0; i < nw; i++) tot += sh[i];
    float inv = 1.0f / tot;
    v.x *= inv; v.y *= inv; v.z *= inv; v.w *= inv;
    *(float4*)(p + tid * 4) = v;
}

// ---------------- LN(a + b + bias) over D=512; 128 threads/row ---------------
__device__ __forceinline__ void ln_finish(float v[4], int tid, const float* g,
                                          const float* be, float* outp)
{
    float s1 = v[0] + v[1] + v[2] + v[3];
    float s2 = v[0] * v[0] + v[1] * v[1] + v[2] * v[2] + v[3] * v[3];
#pragma unroll
    for (int o = 16; o; o >>= 1) {
        s1 += __shfl_xor_sync(~0u, s1, o);
        s2 += __shfl_xor_sync(~0u, s2, o);
    }
    __shared__ float sh1[4], sh2[4];
    if ((tid & 31) == 0) { sh1[tid >> 5] = s1; sh2[tid >> 5] = s2; }
    __syncthreads();
    float rs1 = sh1[0] + sh1[1] + sh1[2] + sh1[3];
    float rs2 = sh2[0] + sh2[1] + sh2[2] + sh2[3];
    float mean = rs1 * (1.0f / 512.0f);
    float var = rs2 * (1.0f / 512.0f) - mean * mean;
    float rstd = rsqrtf(var + 1e-5f);
    float4 g4 = *(const float4*)(g + tid * 4);
    float4 b4 = *(const float4*)(be + tid * 4);
    float4 o4;
    o4.x = (v[0] - mean) * rstd * g4.x + b4.x;
    o4.y = (v[1] - mean) * rstd * g4.y + b4.y;
    o4.z = (v[2] - mean) * rstd * g4.z + b4.z;
    o4.w = (v[3] - mean) * rstd * g4.w + b4.w;
    *(float4*)outp = o4;
}

__global__ __launch_bounds__(128)
void ln_add_k(const float* __restrict__ a, const float* __restrict__ bsrc,
              const float* __restrict__ bias,
              const float* __restrict__ g, const float* __restrict__ be,
              float* __restrict__ out)
{
    const size_t base = (size_t)blockIdx.x * DD;
    const int tid = threadIdx.x;
    float4 va = *(const float4*)(a + base + tid * 4);
    float4 vb = *(const float4*)(bsrc + base + tid * 4);
    float4 vc = *(const float4*)(bias + tid * 4);
    float v[4] = {va.x + vb.x + vc.x, va.y + vb.y + vc.y,
                  va.z + vb.z + vc.z, va.w + vb.w + vc.w};
    ln_finish(v, tid, g, be, out + base + tid * 4);
}

// LN( x1 + linear_interp_upsample(a2) + bias )
__global__ __launch_bounds__(128)
void ln_interp_k(const float* __restrict__ x1, const float* __restrict__ a2,
                 const float* __restrict__ bias,
                 const float* __restrict__ g, const float* __restrict__ be,
                 float* __restrict__ out)
{
    const int r = blockIdx.x;
    const int b = r >> 10, i = r & 1023;
    float src = (i + 0.5f) * 0.5f - 0.5f;
    src = fminf(fmaxf(src, 0.0f), (float)(S2 - 1));
    int i0 = (int)floorf(src);
    int i1 = min(i0 + 1, S2 - 1);
    float w = src - (float)i0;

    const size_t base = (size_t)r * DD;
    const size_t b0 = ((size_t)b * S2 + i0) * DD;
    const size_t b1 = ((size_t)b * S2 + i1) * DD;
    const int tid = threadIdx.x;

    float4 vx = *(const float4*)(x1 + base + tid * 4);
    float4 v0 = *(const float4*)(a2 + b0 + tid * 4);
    float4 v1 = *(const float4*)(a2 + b1 + tid * 4);
    float4 vc = *(const float4*)(bias + tid * 4);
    float v[4];
    v[0] = vx.x + v0.x * (1.f - w) + v1.x * w + vc.x;
    v[1] = vx.y + v0.y * (1.f - w) + v1.y * w + vc.y;
    v[2] = vx.z + v0.z * (1.f - w) + v1.z * w + vc.z;
    v[3] = vx.w + v0.w * (1.f - w) + v1.w * w + vc.w;
    ln_finish(v, tid, g, be, out + base + tid * 4);
}

// avg_pool1d k=2 s=2
__global__ void pool_k(const float* __restrict__ x, float* __restrict__ out)
{
    size_t idx = (size_t)blockIdx.x * 256 + threadIdx.x;
    int d = (int)(idx & 511);
    size_t bt = idx >> 9;
    int t = (int)(bt & (S2 - 1));
    int b = (int)(bt >> 9);
    size_t src = ((size_t)b * SS + 2 * t) * DD + d;
    out[idx] = 0.5f * (x[src] + x[src + DD]);
}

// ---------------- host side ---------------------------------------------------
extern "C" void kernel_launch(void* const* d_in, const int* in_sizes, int n_in,
                              void* d_out, int out_size)
{
    const float* x      = (const float*)d_in[0];
    const float* w_in1  = (const float*)d_in[1];
    const float* b_in1  = (const float*)d_in[2];
    const float* w_out1 = (const float*)d_in[3];
    const float* b_out1 = (const float*)d_in[4];
    const float* w_in2  = (const float*)d_in[5];
    const float* b_in2  = (const float*)d_in[6];
    const float* w_out2 = (const float*)d_in[7];
    const float* b_out2 = (const float*)d_in[8];
    const float* g1     = (const float*)d_in[9];
    const float* beta1  = (const float*)d_in[10];
    const float* g2     = (const float*)d_in[11];
    const float* beta2  = (const float*)d_in[12];
    const float* g3     = (const float*)d_in[13];
    const float* beta3  = (const float*)d_in[14];
    const float* w_ff1  = (const float*)d_in[15];
    const float* b_ff1  = (const float*)d_in[16];
    const float* w_ff2  = (const float*)d_in[17];
    const float* b_ff2  = (const float*)d_in[18];

    float *qkv, *scores, *attn, *x1, *pooled, *a2, *x2, *h, *ff;
    cudaGetSymbolAddress((void**)&qkv,    g_qkv);
    cudaGetSymbolAddress((void**)&scores, g_scores);
    cudaGetSymbolAddress((void**)&attn,   g_attn);
    cudaGetSymbolAddress((void**)&x1,     g_x1);
    cudaGetSymbolAddress((void**)&pooled, g_pooled);
    cudaGetSymbolAddress((void**)&a2,     g_a2);
    cudaGetSymbolAddress((void**)&x2,     g_x2);
    cudaGetSymbolAddress((void**)&h,      g_h);
    cudaGetSymbolAddress((void**)&ff,     g_ff);

    const int M1 = BB * SS;   // 8192
    const int M2 = BB * S2;   // 4096

    // ---- MHA 1 ----
    // qkv = x @ w_in1^T  [8192 x 1536]
    gemm_wmma<128,128,2,4,1><<<dim3(1536/128, M1/128, 1), 256>>>(
        x, 512, 0, 0, w_in1, 512, 0, 0, qkv, 1536, 0, 0, 512, 1.0f);
    bias_act_k<0><<<(size_t)M1*1536/4/256, 256>>>(qkv, b_in1, 1536/4);
    // scores = Q K^T / 8
    gemm_wmma<128,128,2,4,1><<<dim3(SS/128, SS/128, BB*HH), 256>>>(
        qkv, 1536, (long)SS*1536, 64,
        qkv + 512, 1536, (long)SS*1536, 64,
        scores, SS, 8L*SS*SS, (long)SS*SS, 64, 0.125f);
    softmax_fast<<<BB*HH*SS, SS/4>>>(scores);
    // attn = P V
    gemm_wmma<128,64,2,2,0><<<dim3(1, SS/128, BB*HH), 256>>>(
        scores, SS, 8L*SS*SS, (long)SS*SS,
        qkv + 1024, 1536, (long)SS*1536, 64,
        attn, 512, (long)SS*512, 64, SS, 1.0f);
    // out-proj
    gemm_wmma<128,128,2,4,1><<<dim3(512/128, M1/128, 1), 256>>>(
        attn, 512, 0, 0, w_out1, 512, 0, 0, ff, 512, 0, 0, 512, 1.0f);
    ln_add_k<<<M1, 128>>>(x, ff, b_out1, g1, beta1, x1);

    // ---- pool + MHA 2 ----
    pool_k<<<(BB*S2*DD)/256, 256>>>(x1, pooled);
    gemm_wmma<128,128,2,4,1><<<dim3(1536/128, M2/128, 1), 256>>>(
        pooled, 512, 0, 0, w_in2, 512, 0, 0, qkv, 1536, 0, 0, 512, 1.0f);
    bias_act_k<0><<<(size_t)M2*1536/4/256, 256>>>(qkv, b_in2, 1536/4);
    gemm_wmma<128,128,2,4,1><<<dim3(S2/128, S2/128, BB*HH), 256>>>(
        qkv, 1536, (long)S2*1536, 64,
        qkv + 512, 1536, (long)S2*1536, 64,
        scores, S2, 8L*S2*S2, (long)S2*S2, 64, 0.125f);
    softmax_fast<<<BB*HH*S2, S2/4>>>(scores);
    gemm_wmma<128,64,2,2,0><<<dim3(1, S2/128, BB*HH), 256>>>(
        scores, S2, 8L*S2*S2, (long)S2*S2,
        qkv + 1024, 1536, (long)S2*1536, 64,
        attn, 512, (long)S2*512, 64, S2, 1.0f);
    gemm_wmma<128,128,2,4,1><<<dim3(512/128, M2/128, 1), 256>>>(
        attn, 512, 0, 0, w_out2, 512, 0, 0, a2, 512, 0, 0, 512, 1.0f);

    // ---- upsample + residual + LN2 ----
    ln_interp_k<<<M1, 128>>>(x1, a2, b_out2, g2, beta2, x2);

    // ---- FFN ----
    gemm_wmma<128,128,2,4,1><<<dim3(2048/128, M1/128, 1), 256>>>(
        x2, 512, 0, 0, w_ff1, 512, 0, 0, h, 2048, 0, 0, 512, 1.0f);
    bias_act_k<1><<<(size_t)M1*2048/4/256, 256>>>(h, b_ff1, 2048/4);
    gemm_wmma<128,128,2,4,1><<<dim3(512/128, M1/128, 1), 256>>>(
        h, 2048, 0, 0, w_ff2, 2048, 0, 0, ff, 512, 0, 0, 2048, 1.0f);
    ln_add_k<<<M1, 128>>>(x2, ff, b_ff2, g3, beta3, (float*)d_out);
}

// round 4
// speedup vs baseline: 1.7306x; 1.1130x over previous
#include <cuda_runtime.h>
#include <mma.h>
#include <math.h>

using namespace nvcuda;

// Problem constants
#define BB 8
#define SS 1024
#define DD 512
#define HH 8
#define HD 64
#define S2 (SS/2)

// ---------------- scratch (static device globals; no cudaMalloc) -------------
__device__ float g_qkv   [(size_t)BB*SS*3*DD];
__device__ float g_scores[(size_t)BB*HH*SS*SS];
__device__ float g_attn  [(size_t)BB*SS*DD];
__device__ float g_x1    [(size_t)BB*SS*DD];
__device__ float g_pooled[(size_t)BB*S2*DD];
__device__ float g_a2    [(size_t)BB*S2*DD];
__device__ float g_x2    [(size_t)BB*SS*DD];
__device__ float g_h     [(size_t)BB*SS*4*DD];
__device__ float g_ff    [(size_t)BB*SS*DD];

// ---------------- cp.async helpers -------------------------------------------
__device__ __forceinline__ void cp16(float* dst, const float* src)
{
    unsigned sa = (unsigned)__cvta_generic_to_shared(dst);
    asm volatile("cp.async.cg.shared.global [%0], [%1], 16;\n" :: "r"(sa), "l"(src));
}
__device__ __forceinline__ void cp_commit()
{
    asm volatile("cp.async.commit_group;\n");
}

// =====================================================================
// Batched tf32 WMMA GEMM, cp.async double-buffered, BK=32.
//   TRANS_B=1 (NT): C[m,n] = sum_k A[m,k] * B[n,k]   (B row-major [N,K])
//   TRANS_B=0 (NN): C[m,n] = sum_k A[m,k] * B[k,n]   (B row-major [K,N])
// Batch index z -> (b = z>>3, h = z&7); per-matrix strides for b and h.
// M % BM == 0, N % BN == 0, K % 32 == 0.
// =====================================================================
template<int BM, int BN, int WARPS_M, int WARPS_N, int TRANS_B>
__global__ __launch_bounds__(WARPS_M*WARPS_N*32)
void gemm_wmma(const float* __restrict__ A, int ldA, long sAb, long sAh,
               const float* __restrict__ B, int ldB, long sBb, long sBh,
               float* __restrict__ C, int ldC, long sCb, long sCh,
               int K, float scale)
{
    constexpr int TM = BM / (WARPS_M * 16);
    constexpr int TN = BN / (WARPS_N * 16);
    constexpr int NTH = WARPS_M * WARPS_N * 32;
    constexpr int BK = 32;
    constexpr int APAD = 40;                       // row stride (floats): 160B
    constexpr int BROW = TRANS_B ? APAD : (BN + 8);
    constexpr int ASTG = BM * APAD;
    constexpr int BSTG = TRANS_B ? BN * APAD : BK * BROW;

    extern __shared__ __align__(128) float smem[];
    float* As = smem;                  // [2][ASTG]
    float* Bs = smem + 2 * ASTG;       // [2][BSTG]

    const int z = blockIdx.z;
    const int bb = z >> 3, hh = z & 7;
    A += (size_t)bb * sAb + (size_t)hh * sAh;
    B += (size_t)bb * sBb + (size_t)hh * sBh;
    C += (size_t)bb * sCb + (size_t)hh * sCh;

    const int tid = threadIdx.x;
    const int wid = tid >> 5;
    const int warp_m = wid % WARPS_M;
    const int warp_n = wid / WARPS_M;
    const int m0 = blockIdx.y * BM;
    const int n0 = blockIdx.x * BN;

    wmma::fragment<wmma::accumulator, 16, 16, 8, float> acc[TM][TN];
#pragma unroll
    for (int i = 0; i < TM; i++)
#pragma unroll
        for (int j = 0; j < TN; j++) wmma::fill_fragment(acc[i][j], 0.0f);

    const int nt = K / BK;

    // ---- prologue: stage 0 loads ----
    {
        float* as = As;
#pragma unroll
        for (int i = tid; i < BM * BK / 4; i += NTH) {
            int r = i >> 3;            // BK/4 == 8 chunks per row
            int c = (i & 7) * 4;
            cp16(as + r * APAD + c, A + (size_t)(m0 + r) * ldA + c);
        }
        float* bs = Bs;
        if (TRANS_B) {
#pragma unroll
            for (int i = tid; i < BN * BK / 4; i += NTH) {
                int r = i >> 3;
                int c = (i & 7) * 4;
                cp16(bs + r * APAD + c, B + (size_t)(n0 + r) * ldB + c);
            }
        } else {
#pragma unroll
            for (int i = tid; i < BK * BN / 4; i += NTH) {
                int r = i / (BN / 4);
                int c = (i % (BN / 4)) * 4;
                cp16(bs + r * BROW + c, B + (size_t)r * ldB + n0 + c);
            }
        }
        cp_commit();
    }

    for (int it = 0; it < nt; it++) {
        const int cur = it & 1;
        // ---- issue next stage ----
        if (it + 1 < nt) {
            const int k0 = (it + 1) * BK;
            float* as = As + (cur ^ 1) * ASTG;
#pragma unroll
            for (int i = tid; i < BM * BK / 4; i += NTH) {
                int r = i >> 3;
                int c = (i & 7) * 4;
                cp16(as + r * APAD + c, A + (size_t)(m0 + r) * ldA + k0 + c);
            }
            float* bs = Bs + (cur ^ 1) * BSTG;
            if (TRANS_B) {
#pragma unroll
                for (int i = tid; i < BN * BK / 4; i += NTH) {
                    int r = i >> 3;
                    int c = (i & 7) * 4;
                    cp16(bs + r * APAD + c, B + (size_t)(n0 + r) * ldB + k0 + c);
                }
            } else {
#pragma unroll
                for (int i = tid; i < BK * BN / 4; i += NTH) {
                    int r = i / (BN / 4);
                    int c = (i % (BN / 4)) * 4;
                    cp16(bs + r * BROW + c, B + (size_t)(k0 + r) * ldB + n0 + c);
                }
            }
            cp_commit();
            asm volatile("cp.async.wait_group 1;\n");
        } else {
            asm volatile("cp.async.wait_group 0;\n");
        }
        __syncthreads();

        // ---- compute stage `cur` : 4 k-steps of 8 ----
        const float* as = As + cur * ASTG;
        const float* bs = Bs + cur * BSTG;
#pragma unroll
        for (int ks = 0; ks < 4; ks++) {
            const int kk = ks * 8;
            wmma::fragment<wmma::matrix_a, 16, 16, 8, wmma::precision::tf32,
                           wmma::row_major> af[TM];
#pragma unroll
            for (int i = 0; i < TM; i++) {
                wmma::load_matrix_sync(af[i],
                    as + (warp_m * TM * 16 + i * 16) * APAD + kk, APAD);
#pragma unroll
                for (int t = 0; t < af[i].num_elements; t++)
                    af[i].x[t] = wmma::__float_to_tf32(af[i].x[t]);
            }
            if (TRANS_B) {
                wmma::fragment<wmma::matrix_b, 16, 16, 8, wmma::precision::tf32,
                               wmma::col_major> bf[TN];
#pragma unroll
                for (int j = 0; j < TN; j++) {
                    wmma::load_matrix_sync(bf[j],
                        bs + (warp_n * TN * 16 + j * 16) * APAD + kk, APAD);
#pragma unroll
                    for (int t = 0; t < bf[j].num_elements; t++)
                        bf[j].x[t] = wmma::__float_to_tf32(bf[j].x[t]);
                }
#pragma unroll
                for (int i = 0; i < TM; i++)
#pragma unroll
                    for (int j = 0; j < TN; j++)
                        wmma::mma_sync(acc[i][j], af[i], bf[j], acc[i][j]);
            } else {
                wmma::fragment<wmma::matrix_b, 16, 16, 8, wmma::precision::tf32,
                               wmma::row_major> bf[TN];
#pragma unroll
                for (int j = 0; j < TN; j++) {
                    wmma::load_matrix_sync(bf[j],
                        bs + kk * BROW + warp_n * TN * 16 + j * 16, BROW);
#pragma unroll
                    for (int t = 0; t < bf[j].num_elements; t++)
                        bf[j].x[t] = wmma::__float_to_tf32(bf[j].x[t]);
                }
#pragma unroll
                for (int i = 0; i < TM; i++)
#pragma unroll
                    for (int j = 0; j < TN; j++)
                        wmma::mma_sync(acc[i][j], af[i], bf[j], acc[i][j]);
            }
        }
        __syncthreads();
    }

#pragma unroll
    for (int i = 0; i < TM; i++)
#pragma unroll
        for (int j = 0; j < TN; j++) {
#pragma unroll
            for (int t = 0; t < acc[i][j].num_elements; t++)
                acc[i][j].x[t] *= scale;
            wmma::store_matrix_sync(
                C + (size_t)(m0 + warp_m * TM * 16 + i * 16) * ldC
                  + n0 + warp_n * TN * 16 + j * 16,
                acc[i][j], ldC, wmma::mem_row_major);
        }
}

// smem sizes for the two instantiations
#define SMEM_NT ((2*128*40 + 2*128*40) * 4)          // 81920
#define SMEM_NN ((2*128*40 + 2*32*(64+8)) * 4)       // 59392

// ---------------- elementwise bias (+ optional exact GELU) -------------------
template<int GELU>
__global__ void bias_act_k(float* __restrict__ t, const float* __restrict__ bias,
                           int ncols4)
{
    size_t i4 = (size_t)blockIdx.x * blockDim.x + threadIdx.x;
    float4 v = ((float4*)t)[i4];
    int col4 = (int)(i4 % ncols4);
    float4 bv = ((const float4*)bias)[col4];
    v.x += bv.x; v.y += bv.y; v.z += bv.z; v.w += bv.w;
    if (GELU) {
        v.x = 0.5f * v.x * (1.0f + erff(v.x * 0.70710678118654752f));
        v.y = 0.5f * v.y * (1.0f + erff(v.y * 0.70710678118654752f));
        v.z = 0.5f * v.z * (1.0f + erff(v.z * 0.70710678118654752f));
        v.w = 0.5f * v.w * (1.0f + erff(v.w * 0.70710678118654752f));
    }
    ((float4*)t)[i4] = v;
}

// ---------------- register-resident row softmax ------------------------------
__global__ void softmax_fast(float* __restrict__ s)
{
    float* p = s + (size_t)blockIdx.x * (blockDim.x * 4);
    const int tid = threadIdx.x;
    const int wid = tid >> 5, lane = tid & 31;
    const int nw = blockDim.x >> 5;
    __shared__ float sh[8];

    float4 v = *(float4*)(p + tid * 4);
    float mx = fmaxf(fmaxf(v.x, v.y), fmaxf(v.z, v.w));
#pragma unroll
    for (int o = 16; o; o >>= 1) mx = fmaxf(mx, __shfl_xor_sync(~0u, mx, o));
    if (lane == 0) sh[wid] = mx;
    __syncthreads();
    mx = sh[0];
    for (int i = 1; i < nw; i++) mx = fmaxf(mx, sh[i]);
    __syncthreads();

    v.x = __expf(v.x - mx); v.y = __expf(v.y - mx);
    v.z = __expf(v.z - mx); v.w = __expf(v.w - mx);
    float sum = v.x + v.y + v.z + v.w;
#pragma unroll
    for (int o = 16; o; o >>= 1) sum += __shfl_xor_sync(~0u, sum, o);
    if (lane == 0) sh[wid] = sum;
    __syncthreads();
    float tot = 0.f;
    for (int i = 0; i < nw; i++) tot += sh[i];
    float inv = 1.0f / tot;
    v.x *= inv; v.y *= inv; v.z *= inv; v.w *= inv;
    *(float4*)(p + tid * 4) = v;
}

// ---------------- LN(a + b + bias) over D=512; 128 threads/row ---------------
__device__ __forceinline__ void ln_finish(float v[4], int tid, const float* g,
                                          const float* be, float* outp)
{
    float s1 = v[0] + v[1] + v[2] + v[3];
    float s2 = v[0] * v[0] + v[1] * v[1] + v[2] * v[2] + v[3] * v[3];
#pragma unroll
    for (int o = 16; o; o >>= 1) {
        s1 += __shfl_xor_sync(~0u, s1, o);
        s2 += __shfl_xor_sync(~0u, s2, o);
    }
    __shared__ float sh1[4], sh2[4];
    if ((tid & 31) == 0) { sh1[tid >> 5] = s1; sh2[tid >> 5] = s2; }
    __syncthreads();
    float rs1 = sh1[0] + sh1[1] + sh1[2] + sh1[3];
    float rs2 = sh2[0] + sh2[1] + sh2[2] + sh2[3];
    float mean = rs1 * (1.0f / 512.0f);
    float var = rs2 * (1.0f / 512.0f) - mean * mean;
    float rstd = rsqrtf(var + 1e-5f);
    float4 g4 = *(const float4*)(g + tid * 4);
    float4 b4 = *(const float4*)(be + tid * 4);
    float4 o4;
    o4.x = (v[0] - mean) * rstd * g4.x + b4.x;
    o4.y = (v[1] - mean) * rstd * g4.y + b4.y;
    o4.z = (v[2] - mean) * rstd * g4.z + b4.z;
    o4.w = (v[3] - mean) * rstd * g4.w + b4.w;
    *(float4*)outp = o4;
}

__global__ __launch_bounds__(128)
void ln_add_k(const float* __restrict__ a, const float* __restrict__ bsrc,
              const float* __restrict__ bias,
              const float* __restrict__ g, const float* __restrict__ be,
              float* __restrict__ out)
{
    const size_t base = (size_t)blockIdx.x * DD;
    const int tid = threadIdx.x;
    float4 va = *(const float4*)(a + base + tid * 4);
    float4 vb = *(const float4*)(bsrc + base + tid * 4);
    float4 vc = *(const float4*)(bias + tid * 4);
    float v[4] = {va.x + vb.x + vc.x, va.y + vb.y + vc.y,
                  va.z + vb.z + vc.z, va.w + vb.w + vc.w};
    ln_finish(v, tid, g, be, out + base + tid * 4);
}

__global__ __launch_bounds__(128)
void ln_interp_k(const float* __restrict__ x1, const float* __restrict__ a2,
                 const float* __restrict__ bias,
                 const float* __restrict__ g, const float* __restrict__ be,
                 float* __restrict__ out)
{
    const int r = blockIdx.x;
    const int b = r >> 10, i = r & 1023;
    float src = (i + 0.5f) * 0.5f - 0.5f;
    src = fminf(fmaxf(src, 0.0f), (float)(S2 - 1));
    int i0 = (int)floorf(src);
    int i1 = min(i0 + 1, S2 - 1);
    float w = src - (float)i0;

    const size_t base = (size_t)r * DD;
    const size_t b0 = ((size_t)b * S2 + i0) * DD;
    const size_t b1 = ((size_t)b * S2 + i1) * DD;
    const int tid = threadIdx.x;

    float4 vx = *(const float4*)(x1 + base + tid * 4);
    float4 v0 = *(const float4*)(a2 + b0 + tid * 4);
    float4 v1 = *(const float4*)(a2 + b1 + tid * 4);
    float4 vc = *(const float4*)(bias + tid * 4);
    float v[4];
    v[0] = vx.x + v0.x * (1.f - w) + v1.x * w + vc.x;
    v[1] = vx.y + v0.y * (1.f - w) + v1.y * w + vc.y;
    v[2] = vx.z + v0.z * (1.f - w) + v1.z * w + vc.z;
    v[3] = vx.w + v0.w * (1.f - w) + v1.w * w + vc.w;
    ln_finish(v, tid, g, be, out + base + tid * 4);
}

// avg_pool1d k=2 s=2
__global__ void pool_k(const float* __restrict__ x, float* __restrict__ out)
{
    size_t idx = (size_t)blockIdx.x * 256 + threadIdx.x;
    int d = (int)(idx & 511);
    size_t bt = idx >> 9;
    int t = (int)(bt & (S2 - 1));
    int b = (int)(bt >> 9);
    size_t src = ((size_t)b * SS + 2 * t) * DD + d;
    out[idx] = 0.5f * (x[src] + x[src + DD]);
}

// ---------------- host side ---------------------------------------------------
extern "C" void kernel_launch(void* const* d_in, const int* in_sizes, int n_in,
                              void* d_out, int out_size)
{
    const float* x      = (const float*)d_in[0];
    const float* w_in1  = (const float*)d_in[1];
    const float* b_in1  = (const float*)d_in[2];
    const float* w_out1 = (const float*)d_in[3];
    const float* b_out1 = (const float*)d_in[4];
    const float* w_in2  = (const float*)d_in[5];
    const float* b_in2  = (const float*)d_in[6];
    const float* w_out2 = (const float*)d_in[7];
    const float* b_out2 = (const float*)d_in[8];
    const float* g1     = (const float*)d_in[9];
    const float* beta1  = (const float*)d_in[10];
    const float* g2     = (const float*)d_in[11];
    const float* beta2  = (const float*)d_in[12];
    const float* g3     = (const float*)d_in[13];
    const float* beta3  = (const float*)d_in[14];
    const float* w_ff1  = (const float*)d_in[15];
    const float* b_ff1  = (const float*)d_in[16];
    const float* w_ff2  = (const float*)d_in[17];
    const float* b_ff2  = (const float*)d_in[18];

    float *qkv, *scores, *attn, *x1, *pooled, *a2, *x2, *h, *ff;
    cudaGetSymbolAddress((void**)&qkv,    g_qkv);
    cudaGetSymbolAddress((void**)&scores, g_scores);
    cudaGetSymbolAddress((void**)&attn,   g_attn);
    cudaGetSymbolAddress((void**)&x1,     g_x1);
    cudaGetSymbolAddress((void**)&pooled, g_pooled);
    cudaGetSymbolAddress((void**)&a2,     g_a2);
    cudaGetSymbolAddress((void**)&x2,     g_x2);
    cudaGetSymbolAddress((void**)&h,      g_h);
    cudaGetSymbolAddress((void**)&ff,     g_ff);

    cudaFuncSetAttribute(gemm_wmma<128,128,2,4,1>,
                         cudaFuncAttributeMaxDynamicSharedMemorySize, SMEM_NT);
    cudaFuncSetAttribute(gemm_wmma<128,64,4,2,0>,
                         cudaFuncAttributeMaxDynamicSharedMemorySize, SMEM_NN);

    const int M1 = BB * SS;   // 8192
    const int M2 = BB * S2;   // 4096

    // ---- MHA 1 ----
    gemm_wmma<128,128,2,4,1><<<dim3(1536/128, M1/128, 1), 256, SMEM_NT>>>(
        x, 512, 0, 0, w_in1, 512, 0, 0, qkv, 1536, 0, 0, 512, 1.0f);
    bias_act_k<0><<<(size_t)M1*1536/4/256, 256>>>(qkv, b_in1, 1536/4);
    gemm_wmma<128,128,2,4,1><<<dim3(SS/128, SS/128, BB*HH), 256, SMEM_NT>>>(
        qkv, 1536, (long)SS*1536, 64,
        qkv + 512, 1536, (long)SS*1536, 64,
        scores, SS, 8L*SS*SS, (long)SS*SS, 64, 0.125f);
    softmax_fast<<<BB*HH*SS, SS/4>>>(scores);
    gemm_wmma<128,64,4,2,0><<<dim3(1, SS/128, BB*HH), 256, SMEM_NN>>>(
        scores, SS, 8L*SS*SS, (long)SS*SS,
        qkv + 1024, 1536, (long)SS*1536, 64,
        attn, 512, (long)SS*512, 64, SS, 1.0f);
    gemm_wmma<128,128,2,4,1><<<dim3(512/128, M1/128, 1), 256, SMEM_NT>>>(
        attn, 512, 0, 0, w_out1, 512, 0, 0, ff, 512, 0, 0, 512, 1.0f);
    ln_add_k<<<M1, 128>>>(x, ff, b_out1, g1, beta1, x1);

    // ---- pool + MHA 2 ----
    pool_k<<<(BB*S2*DD)/256, 256>>>(x1, pooled);
    gemm_wmma<128,128,2,4,1><<<dim3(1536/128, M2/128, 1), 256, SMEM_NT>>>(
        pooled, 512, 0, 0, w_in2, 512, 0, 0, qkv, 1536, 0, 0, 512, 1.0f);
    bias_act_k<0><<<(size_t)M2*1536/4/256, 256>>>(qkv, b_in2, 1536/4);
    gemm_wmma<128,128,2,4,1><<<dim3(S2/128, S2/128, BB*HH), 256, SMEM_NT>>>(
        qkv, 1536, (long)S2*1536, 64,
        qkv + 512, 1536, (long)S2*1536, 64,
        scores, S2, 8L*S2*S2, (long)S2*S2, 64, 0.125f);
    softmax_fast<<<BB*HH*S2, S2/4>>>(scores);
    gemm_wmma<128,64,4,2,0><<<dim3(1, S2/128, BB*HH), 256, SMEM_NN>>>(
        scores, S2, 8L*S2*S2, (long)S2*S2,
        qkv + 1024, 1536, (long)S2*1536, 64,
        attn, 512, (long)S2*512, 64, S2, 1.0f);
    gemm_wmma<128,128,2,4,1><<<dim3(512/128, M2/128, 1), 256, SMEM_NT>>>(
        attn, 512, 0, 0, w_out2, 512, 0, 0, a2, 512, 0, 0, 512, 1.0f);

    // ---- upsample + residual + LN2 ----
    ln_interp_k<<<M1, 128>>>(x1, a2, b_out2, g2, beta2, x2);

    // ---- FFN ----
    gemm_wmma<128,128,2,4,1><<<dim3(2048/128, M1/128, 1), 256, SMEM_NT>>>(
        x2, 512, 0, 0, w_ff1, 512, 0, 0, h, 2048, 0, 0, 512, 1.0f);
    bias_act_k<1><<<(size_t)M1*2048/4/256, 256>>>(h, b_ff1, 2048/4);
    gemm_wmma<128,128,2,4,1><<<dim3(512/128, M1/128, 1), 256, SMEM_NT>>>(
        h, 2048, 0, 0, w_ff2, 2048, 0, 0, ff, 512, 0, 0, 2048, 1.0f);
    ln_add_k<<<M1, 128>>>(x2, ff, b_ff2, g3, beta3, (float*)d_out);
}

// round 6
// speedup vs baseline: 1.9104x; 1.1039x over previous
#include <cuda_runtime.h>
#include <mma.h>
#include <math.h>

using namespace nvcuda;

// Problem constants
#define BB 8
#define SS 1024
#define DD 512
#define HH 8
#define HD 64
#define S2 (SS/2)

// ---------------- scratch (static device globals; no cudaMalloc) -------------
__device__ float g_qkv   [(size_t)BB*SS*3*DD];
__device__ float g_attn  [(size_t)BB*SS*DD];
__device__ float g_x1    [(size_t)BB*SS*DD];
__device__ float g_pooled[(size_t)BB*S2*DD];
__device__ float g_a2    [(size_t)BB*S2*DD];
__device__ float g_x2    [(size_t)BB*SS*DD];
__device__ float g_h     [(size_t)BB*SS*4*DD];
__device__ float g_ff    [(size_t)BB*SS*DD];

// ---------------- cp.async helpers -------------------------------------------
__device__ __forceinline__ void cp16(float* dst, const float* src)
{
    unsigned sa = (unsigned)__cvta_generic_to_shared(dst);
    asm volatile("cp.async.cg.shared.global [%0], [%1], 16;\n" :: "r"(sa), "l"(src));
}
__device__ __forceinline__ void cp_commit()
{
    asm volatile("cp.async.commit_group;\n");
}

// =====================================================================
// Batched tf32 WMMA GEMM, cp.async double-buffered, BK=32.
// (fp32 fed to tf32 mma without cvt -> hw truncation; saves ALU issue)
// =====================================================================
template<int BM, int BN, int WARPS_M, int WARPS_N, int TRANS_B>
__global__ __launch_bounds__(WARPS_M*WARPS_N*32)
void gemm_wmma(const float* __restrict__ A, int ldA, long sAb, long sAh,
               const float* __restrict__ B, int ldB, long sBb, long sBh,
               float* __restrict__ C, int ldC, long sCb, long sCh,
               int K, float scale)
{
    constexpr int TM = BM / (WARPS_M * 16);
    constexpr int TN = BN / (WARPS_N * 16);
    constexpr int NTH = WARPS_M * WARPS_N * 32;
    constexpr int BK = 32;
    constexpr int APAD = 40;
    constexpr int BROW = TRANS_B ? APAD : (BN + 8);
    constexpr int ASTG = BM * APAD;
    constexpr int BSTG = TRANS_B ? BN * APAD : BK * BROW;

    extern __shared__ __align__(128) float smem[];
    float* As = smem;
    float* Bs = smem + 2 * ASTG;

    const int z = blockIdx.z;
    const int bb = z >> 3, hh = z & 7;
    A += (size_t)bb * sAb + (size_t)hh * sAh;
    B += (size_t)bb * sBb + (size_t)hh * sBh;
    C += (size_t)bb * sCb + (size_t)hh * sCh;

    const int tid = threadIdx.x;
    const int wid = tid >> 5;
    const int warp_m = wid % WARPS_M;
    const int warp_n = wid / WARPS_M;
    const int m0 = blockIdx.y * BM;
    const int n0 = blockIdx.x * BN;

    wmma::fragment<wmma::accumulator, 16, 16, 8, float> acc[TM][TN];
#pragma unroll
    for (int i = 0; i < TM; i++)
#pragma unroll
        for (int j = 0; j < TN; j++) wmma::fill_fragment(acc[i][j], 0.0f);

    const int nt = K / BK;

    {
        float* as = As;
#pragma unroll
        for (int i = tid; i < BM * BK / 4; i += NTH) {
            int r = i >> 3;
            int c = (i & 7) * 4;
            cp16(as + r * APAD + c, A + (size_t)(m0 + r) * ldA + c);
        }
        float* bs = Bs;
        if (TRANS_B) {
#pragma unroll
            for (int i = tid; i < BN * BK / 4; i += NTH) {
                int r = i >> 3;
                int c = (i & 7) * 4;
                cp16(bs + r * APAD + c, B + (size_t)(n0 + r) * ldB + c);
            }
        } else {
#pragma unroll
            for (int i = tid; i < BK * BN / 4; i += NTH) {
                int r = i / (BN / 4);
                int c = (i % (BN / 4)) * 4;
                cp16(bs + r * BROW + c, B + (size_t)r * ldB + n0 + c);
            }
        }
        cp_commit();
    }

    for (int it = 0; it < nt; it++) {
        const int cur = it & 1;
        if (it + 1 < nt) {
            const int k0 = (it + 1) * BK;
            float* as = As + (cur ^ 1) * ASTG;
#pragma unroll
            for (int i = tid; i < BM * BK / 4; i += NTH) {
                int r = i >> 3;
                int c = (i & 7) * 4;
                cp16(as + r * APAD + c, A + (size_t)(m0 + r) * ldA + k0 + c);
            }
            float* bs = Bs + (cur ^ 1) * BSTG;
            if (TRANS_B) {
#pragma unroll
                for (int i = tid; i < BN * BK / 4; i += NTH) {
                    int r = i >> 3;
                    int c = (i & 7) * 4;
                    cp16(bs + r * APAD + c, B + (size_t)(n0 + r) * ldB + k0 + c);
                }
            } else {
#pragma unroll
                for (int i = tid; i < BK * BN / 4; i += NTH) {
                    int r = i / (BN / 4);
                    int c = (i % (BN / 4)) * 4;
                    cp16(bs + r * BROW + c, B + (size_t)(k0 + r) * ldB + n0 + c);
                }
            }
            cp_commit();
            asm volatile("cp.async.wait_group 1;\n");
        } else {
            asm volatile("cp.async.wait_group 0;\n");
        }
        __syncthreads();

        const float* as = As + cur * ASTG;
        const float* bs = Bs + cur * BSTG;
#pragma unroll
        for (int ks = 0; ks < 4; ks++) {
            const int kk = ks * 8;
            wmma::fragment<wmma::matrix_a, 16, 16, 8, wmma::precision::tf32,
                           wmma::row_major> af[TM];
#pragma unroll
            for (int i = 0; i < TM; i++)
                wmma::load_matrix_sync(af[i],
                    as + (warp_m * TM * 16 + i * 16) * APAD + kk, APAD);
            if (TRANS_B) {
                wmma::fragment<wmma::matrix_b, 16, 16, 8, wmma::precision::tf32,
                               wmma::col_major> bf[TN];
#pragma unroll
                for (int j = 0; j < TN; j++)
                    wmma::load_matrix_sync(bf[j],
                        bs + (warp_n * TN * 16 + j * 16) * APAD + kk, APAD);
#pragma unroll
                for (int i = 0; i < TM; i++)
#pragma unroll
                    for (int j = 0; j < TN; j++)
                        wmma::mma_sync(acc[i][j], af[i], bf[j], acc[i][j]);
            } else {
                wmma::fragment<wmma::matrix_b, 16, 16, 8, wmma::precision::tf32,
                               wmma::row_major> bf[TN];
#pragma unroll
                for (int j = 0; j < TN; j++)
                    wmma::load_matrix_sync(bf[j],
                        bs + kk * BROW + warp_n * TN * 16 + j * 16, BROW);
#pragma unroll
                for (int i = 0; i < TM; i++)
#pragma unroll
                    for (int j = 0; j < TN; j++)
                        wmma::mma_sync(acc[i][j], af[i], bf[j], acc[i][j]);
            }
        }
        __syncthreads();
    }

#pragma unroll
    for (int i = 0; i < TM; i++)
#pragma unroll
        for (int j = 0; j < TN; j++) {
#pragma unroll
            for (int t = 0; t < acc[i][j].num_elements; t++)
                acc[i][j].x[t] *= scale;
            wmma::store_matrix_sync(
                C + (size_t)(m0 + warp_m * TM * 16 + i * 16) * ldC
                  + n0 + warp_n * TN * 16 + j * 16,
                acc[i][j], ldC, wmma::mem_row_major);
        }
}

#define SMEM_NT ((2*128*40 + 2*128*40) * 4)

// =====================================================================
// Fused flash attention: per block, 128 Q rows of one (b,h); stream K/V
// in 64-key tiles; online softmax; O in thread-owned registers.
// qkv layout [b, s, 1536]: q at h*64, k at 512+h*64, v at 1024+h*64.
// 256 threads = 8 warps in 4x2 grid; warp tile 32x32 of the 128x64 S-tile.
// =====================================================================
#define FA_PAD 72
#define FA_SMEM ((128*FA_PAD + 64*FA_PAD + 64*FA_PAD + 128*FA_PAD) * 4)  // 110592

template<int SQ>
__global__ __launch_bounds__(256)
void flash_attn(const float* __restrict__ qkv, float* __restrict__ attn)
{
    extern __shared__ __align__(128) float smem[];
    float* Qs = smem;                         // 128 x 72
    float* Ks = Qs + 128 * FA_PAD;            // 64 x 72
    float* Vs = Ks + 64 * FA_PAD;             // 64 x 72
    float* Ss = Vs + 64 * FA_PAD;             // 128 x 72  (S -> P -> PV)

    const int z = blockIdx.z;
    const int bb = z >> 3, hh = z & 7;
    const int q0 = blockIdx.y * 128;
    const float* Qg = qkv + (size_t)bb * SQ * 1536 + hh * 64;
    const float* Kg = Qg + 512;
    const float* Vg = Qg + 1024;

    const int tid = threadIdx.x;
    const int wid = tid >> 5;
    const int warp_m = wid & 3;     // 0..3  (32-row slab)
    const int warp_n = wid >> 2;    // 0..1  (32-col slab)

    // per-thread softmax/O ownership: row = tid>>1, col half = tid&1
    const int row = tid >> 1;
    const int cbase = (tid & 1) * 32;

    // ---- stage Q tile ----
#pragma unroll
    for (int i = tid; i < 128 * 16; i += 256) {
        int r = i >> 4;
        int c = (i & 15) * 4;
        cp16(Qs + r * FA_PAD + c, Qg + (size_t)(q0 + r) * 1536 + c);
    }
    cp_commit();

    float m_run = -1e30f, l_run = 0.0f;
    float O[32];
#pragma unroll
    for (int c = 0; c < 32; c++) O[c] = 0.0f;

    const int NT = SQ / 64;
    for (int kt = 0; kt < NT; kt++) {
        // ---- load K/V tiles ----
#pragma unroll
        for (int i = tid; i < 64 * 16; i += 256) {
            int r = i >> 4;
            int c = (i & 15) * 4;
            cp16(Ks + r * FA_PAD + c, Kg + (size_t)(kt * 64 + r) * 1536 + c);
            cp16(Vs + r * FA_PAD + c, Vg + (size_t)(kt * 64 + r) * 1536 + c);
        }
        cp_commit();
        asm volatile("cp.async.wait_group 0;\n");
        __syncthreads();

        // ---- S = Q K^T (128x64, k=64) ----
        wmma::fragment<wmma::accumulator, 16, 16, 8, float> sacc[2][2];
#pragma unroll
        for (int i = 0; i < 2; i++)
#pragma unroll
            for (int j = 0; j < 2; j++) wmma::fill_fragment(sacc[i][j], 0.0f);
#pragma unroll
        for (int ks = 0; ks < 8; ks++) {
            const int kk = ks * 8;
            wmma::fragment<wmma::matrix_a, 16, 16, 8, wmma::precision::tf32,
                           wmma::row_major> af[2];
            wmma::fragment<wmma::matrix_b, 16, 16, 8, wmma::precision::tf32,
                           wmma::col_major> bf[2];
#pragma unroll
            for (int i = 0; i < 2; i++)
                wmma::load_matrix_sync(af[i],
                    Qs + (warp_m * 32 + i * 16) * FA_PAD + kk, FA_PAD);
#pragma unroll
            for (int j = 0; j < 2; j++)
                wmma::load_matrix_sync(bf[j],
                    Ks + (warp_n * 32 + j * 16) * FA_PAD + kk, FA_PAD);
#pragma unroll
            for (int i = 0; i < 2; i++)
#pragma unroll
                for (int j = 0; j < 2; j++)
                    wmma::mma_sync(sacc[i][j], af[i], bf[j], sacc[i][j]);
        }
        // scale by 1/sqrt(64) and store to Ss
#pragma unroll
        for (int i = 0; i < 2; i++)
#pragma unroll
            for (int j = 0; j < 2; j++) {
#pragma unroll
                for (int t = 0; t < sacc[i][j].num_elements; t++)
                    sacc[i][j].x[t] *= 0.125f;
                wmma::store_matrix_sync(
                    Ss + (warp_m * 32 + i * 16) * FA_PAD + warp_n * 32 + j * 16,
                    sacc[i][j], FA_PAD, wmma::mem_row_major);
            }
        __syncthreads();

        // ---- online softmax on Ss rows (2 threads per row) ----
        float* rp = Ss + row * FA_PAD + cbase;
        float mx = -1e30f;
#pragma unroll
        for (int c = 0; c < 32; c++) mx = fmaxf(mx, rp[c]);
        mx = fmaxf(mx, __shfl_xor_sync(~0u, mx, 1));
        float m_new = fmaxf(m_run, mx);
        float alpha = __expf(m_run - m_new);
        float sum = 0.0f;
#pragma unroll
        for (int c = 0; c < 32; c++) {
            float p = __expf(rp[c] - m_new);
            rp[c] = p;
            sum += p;
        }
        sum += __shfl_xor_sync(~0u, sum, 1);
        l_run = l_run * alpha + sum;
        m_run = m_new;
        __syncthreads();

        // ---- PV = P @ V (128x64, k=64) ----
        wmma::fragment<wmma::accumulator, 16, 16, 8, float> oacc[2][2];
#pragma unroll
        for (int i = 0; i < 2; i++)
#pragma unroll
            for (int j = 0; j < 2; j++) wmma::fill_fragment(oacc[i][j], 0.0f);
#pragma unroll
        for (int ks = 0; ks < 8; ks++) {
            const int kk = ks * 8;
            wmma::fragment<wmma::matrix_a, 16, 16, 8, wmma::precision::tf32,
                           wmma::row_major> af[2];
            wmma::fragment<wmma::matrix_b, 16, 16, 8, wmma::precision::tf32,
                           wmma::row_major> bf[2];
#pragma unroll
            for (int i = 0; i < 2; i++)
                wmma::load_matrix_sync(af[i],
                    Ss + (warp_m * 32 + i * 16) * FA_PAD + kk, FA_PAD);
#pragma unroll
            for (int j = 0; j < 2; j++)
                wmma::load_matrix_sync(bf[j],
                    Vs + kk * FA_PAD + warp_n * 32 + j * 16, FA_PAD);
#pragma unroll
            for (int i = 0; i < 2; i++)
#pragma unroll
                for (int j = 0; j < 2; j++)
                    wmma::mma_sync(oacc[i][j], af[i], bf[j], oacc[i][j]);
        }
        __syncthreads();   // all P reads done before overwrite
#pragma unroll
        for (int i = 0; i < 2; i++)
#pragma unroll
            for (int j = 0; j < 2; j++)
                wmma::store_matrix_sync(
                    Ss + (warp_m * 32 + i * 16) * FA_PAD + warp_n * 32 + j * 16,
                    oacc[i][j], FA_PAD, wmma::mem_row_major);
        __syncthreads();

        // ---- merge: O = O*alpha + PV ----
#pragma unroll
        for (int c = 0; c < 32; c++)
            O[c] = O[c] * alpha + rp[c];
        __syncthreads();   // Ss free for next iteration
    }

    // ---- epilogue: O / l_run -> attn[b, q0+row, h*64 + cbase + c] ----
    float inv = 1.0f / l_run;
    float* outp = attn + ((size_t)bb * SQ + q0 + row) * 512 + hh * 64 + cbase;
#pragma unroll
    for (int c4 = 0; c4 < 8; c4++) {
        float4 v;
        v.x = O[c4*4+0] * inv; v.y = O[c4*4+1] * inv;
        v.z = O[c4*4+2] * inv; v.w = O[c4*4+3] * inv;
        *(float4*)(outp + c4 * 4) = v;
    }
}

// ---------------- elementwise bias (+ optional exact GELU) -------------------
template<int GELU>
__global__ void bias_act_k(float* __restrict__ t, const float* __restrict__ bias,
                           int ncols4)
{
    size_t i4 = (size_t)blockIdx.x * blockDim.x + threadIdx.x;
    float4 v = ((float4*)t)[i4];
    int col4 = (int)(i4 % ncols4);
    float4 bv = ((const float4*)bias)[col4];
    v.x += bv.x; v.y += bv.y; v.z += bv.z; v.w += bv.w;
    if (GELU) {
        v.x = 0.5f * v.x * (1.0f + erff(v.x * 0.70710678118654752f));
        v.y = 0.5f * v.y * (1.0f + erff(v.y * 0.70710678118654752f));
        v.z = 0.5f * v.z * (1.0f + erff(v.z * 0.70710678118654752f));
        v.w = 0.5f * v.w * (1.0f + erff(v.w * 0.70710678118654752f));
    }
    ((float4*)t)[i4] = v;
}

// ---------------- LN(a + b + bias) over D=512; 128 threads/row ---------------
__device__ __forceinline__ void ln_finish(float v[4], int tid, const float* g,
                                          const float* be, float* outp)
{
    float s1 = v[0] + v[1] + v[2] + v[3];
    float s2 = v[0] * v[0] + v[1] * v[1] + v[2] * v[2] + v[3] * v[3];
#pragma unroll
    for (int o = 16; o; o >>= 1) {
        s1 += __shfl_xor_sync(~0u, s1, o);
        s2 += __shfl_xor_sync(~0u, s2, o);
    }
    __shared__ float sh1[4], sh2[4];
    if ((tid & 31) == 0) { sh1[tid >> 5] = s1; sh2[tid >> 5] = s2; }
    __syncthreads();
    float rs1 = sh1[0] + sh1[1] + sh1[2] + sh1[3];
    float rs2 = sh2[0] + sh2[1] + sh2[2] + sh2[3];
    float mean = rs1 * (1.0f / 512.0f);
    float var = rs2 * (1.0f / 512.0f) - mean * mean;
    float rstd = rsqrtf(var + 1e-5f);
    float4 g4 = *(const float4*)(g + tid * 4);
    float4 b4 = *(const float4*)(be + tid * 4);
    float4 o4;
    o4.x = (v[0] - mean) * rstd * g4.x + b4.x;
    o4.y = (v[1] - mean) * rstd * g4.y + b4.y;
    o4.z = (v[2] - mean) * rstd * g4.z + b4.z;
    o4.w = (v[3] - mean) * rstd * g4.w + b4.w;
    *(float4*)outp = o4;
}

__global__ __launch_bounds__(128)
void ln_add_k(const float* __restrict__ a, const float* __restrict__ bsrc,
              const float* __restrict__ bias,
              const float* __restrict__ g, const float* __restrict__ be,
              float* __restrict__ out)
{
    const size_t base = (size_t)blockIdx.x * DD;
    const int tid = threadIdx.x;
    float4 va = *(const float4*)(a + base + tid * 4);
    float4 vb = *(const float4*)(bsrc + base + tid * 4);
    float4 vc = *(const float4*)(bias + tid * 4);
    float v[4] = {va.x + vb.x + vc.x, va.y + vb.y + vc.y,
                  va.z + vb.z + vc.z, va.w + vb.w + vc.w};
    ln_finish(v, tid, g, be, out + base + tid * 4);
}

__global__ __launch_bounds__(128)
void ln_interp_k(const float* __restrict__ x1, const float* __restrict__ a2,
                 const float* __restrict__ bias,
                 const float* __restrict__ g, const float* __restrict__ be,
                 float* __restrict__ out)
{
    const int r = blockIdx.x;
    const int b = r >> 10, i = r & 1023;
    float src = (i + 0.5f) * 0.5f - 0.5f;
    src = fminf(fmaxf(src, 0.0f), (float)(S2 - 1));
    int i0 = (int)floorf(src);
    int i1 = min(i0 + 1, S2 - 1);
    float w = src - (float)i0;

    const size_t base = (size_t)r * DD;
    const size_t b0 = ((size_t)b * S2 + i0) * DD;
    const size_t b1 = ((size_t)b * S2 + i1) * DD;
    const int tid = threadIdx.x;

    float4 vx = *(const float4*)(x1 + base + tid * 4);
    float4 v0 = *(const float4*)(a2 + b0 + tid * 4);
    float4 v1 = *(const float4*)(a2 + b1 + tid * 4);
    float4 vc = *(const float4*)(bias + tid * 4);
    float v[4];
    v[0] = vx.x + v0.x * (1.f - w) + v1.x * w + vc.x;
    v[1] = vx.y + v0.y * (1.f - w) + v1.y * w + vc.y;
    v[2] = vx.z + v0.z * (1.f - w) + v1.z * w + vc.z;
    v[3] = vx.w + v0.w * (1.f - w) + v1.w * w + vc.w;
    ln_finish(v, tid, g, be, out + base + tid * 4);
}

// avg_pool1d k=2 s=2
__global__ void pool_k(const float* __restrict__ x, float* __restrict__ out)
{
    size_t idx = (size_t)blockIdx.x * 256 + threadIdx.x;
    int d = (int)(idx & 511);
    size_t bt = idx >> 9;
    int t = (int)(bt & (S2 - 1));
    int b = (int)(bt >> 9);
    size_t src = ((size_t)b * SS + 2 * t) * DD + d;
    out[idx] = 0.5f * (x[src] + x[src + DD]);
}

// ---------------- host side ---------------------------------------------------
extern "C" void kernel_launch(void* const* d_in, const int* in_sizes, int n_in,
                              void* d_out, int out_size)
{
    const float* x      = (const float*)d_in[0];
    const float* w_in1  = (const float*)d_in[1];
    const float* b_in1  = (const float*)d_in[2];
    const float* w_out1 = (const float*)d_in[3];
    const float* b_out1 = (const float*)d_in[4];
    const float* w_in2  = (const float*)d_in[5];
    const float* b_in2  = (const float*)d_in[6];
    const float* w_out2 = (const float*)d_in[7];
    const float* b_out2 = (const float*)d_in[8];
    const float* g1     = (const float*)d_in[9];
    const float* beta1  = (const float*)d_in[10];
    const float* g2     = (const float*)d_in[11];
    const float* beta2  = (const float*)d_in[12];
    const float* g3     = (const float*)d_in[13];
    const float* beta3  = (const float*)d_in[14];
    const float* w_ff1  = (const float*)d_in[15];
    const float* b_ff1  = (const float*)d_in[16];
    const float* w_ff2  = (const float*)d_in[17];
    const float* b_ff2  = (const float*)d_in[18];

    float *qkv, *attn, *x1, *pooled, *a2, *x2, *h, *ff;
    cudaGetSymbolAddress((void**)&qkv,    g_qkv);
    cudaGetSymbolAddress((void**)&attn,   g_attn);
    cudaGetSymbolAddress((void**)&x1,     g_x1);
    cudaGetSymbolAddress((void**)&pooled, g_pooled);
    cudaGetSymbolAddress((void**)&a2,     g_a2);
    cudaGetSymbolAddress((void**)&x2,     g_x2);
    cudaGetSymbolAddress((void**)&h,      g_h);
    cudaGetSymbolAddress((void**)&ff,     g_ff);

    cudaFuncSetAttribute(gemm_wmma<128,128,2,4,1>,
                         cudaFuncAttributeMaxDynamicSharedMemorySize, SMEM_NT);
    cudaFuncSetAttribute(flash_attn<SS>,
                         cudaFuncAttributeMaxDynamicSharedMemorySize, FA_SMEM);
    cudaFuncSetAttribute(flash_attn<S2>,
                         cudaFuncAttributeMaxDynamicSharedMemorySize, FA_SMEM);

    const int M1 = BB * SS;   // 8192
    const int M2 = BB * S2;   // 4096

    // ---- MHA 1 ----
    gemm_wmma<128,128,2,4,1><<<dim3(1536/128, M1/128, 1), 256, SMEM_NT>>>(
        x, 512, 0, 0, w_in1, 512, 0, 0, qkv, 1536, 0, 0, 512, 1.0f);
    bias_act_k<0><<<(size_t)M1*1536/4/256, 256>>>(qkv, b_in1, 1536/4);
    flash_attn<SS><<<dim3(1, SS/128, BB*HH), 256, FA_SMEM>>>(qkv, attn);
    gemm_wmma<128,128,2,4,1><<<dim3(512/128, M1/128, 1), 256, SMEM_NT>>>(
        attn, 512, 0, 0, w_out1, 512, 0, 0, ff, 512, 0, 0, 512, 1.0f);
    ln_add_k<<<M1, 128>>>(x, ff, b_out1, g1, beta1, x1);

    // ---- pool + MHA 2 ----
    pool_k<<<(BB*S2*DD)/256, 256>>>(x1, pooled);
    gemm_wmma<128,128,2,4,1><<<dim3(1536/128, M2/128, 1), 256, SMEM_NT>>>(
        pooled, 512, 0, 0, w_in2, 512, 0, 0, qkv, 1536, 0, 0, 512, 1.0f);
    bias_act_k<0><<<(size_t)M2*1536/4/256, 256>>>(qkv, b_in2, 1536/4);
    flash_attn<S2><<<dim3(1, S2/128, BB*HH), 256, FA_SMEM>>>(qkv, attn);
    gemm_wmma<128,128,2,4,1><<<dim3(512/128, M2/128, 1), 256, SMEM_NT>>>(
        attn, 512, 0, 0, w_out2, 512, 0, 0, a2, 512, 0, 0, 512, 1.0f);

    // ---- upsample + residual + LN2 ----
    ln_interp_k<<<M1, 128>>>(x1, a2, b_out2, g2, beta2, x2);

    // ---- FFN ----
    gemm_wmma<128,128,2,4,1><<<dim3(2048/128, M1/128, 1), 256, SMEM_NT>>>(
        x2, 512, 0, 0, w_ff1, 512, 0, 0, h, 2048, 0, 0, 512, 1.0f);
    bias_act_k<1><<<(size_t)M1*2048/4/256, 256>>>(h, b_ff1, 2048/4);
    gemm_wmma<128,128,2,4,1><<<dim3(512/128, M1/128, 1), 256, SMEM_NT>>>(
        h, 2048, 0, 0, w_ff2, 2048, 0, 0, ff, 512, 0, 0, 2048, 1.0f);
    ln_add_k<<<M1, 128>>>(x2, ff, b_ff2, g3, beta3, (float*)d_out);
}

// round 7
// speedup vs baseline: 2.0252x; 1.0601x over previous
#include <cuda_runtime.h>
#include <mma.h>
#include <math.h>

using namespace nvcuda;

// Problem constants
#define BB 8
#define SS 1024
#define DD 512
#define HH 8
#define HD 64
#define S2 (SS/2)

// ---------------- scratch (static device globals; no cudaMalloc) -------------
__device__ float g_qkv   [(size_t)BB*SS*3*DD];
__device__ float g_attn  [(size_t)BB*SS*DD];
__device__ float g_x1    [(size_t)BB*SS*DD];
__device__ float g_pooled[(size_t)BB*S2*DD];
__device__ float g_a2    [(size_t)BB*S2*DD];
__device__ float g_x2    [(size_t)BB*SS*DD];
__device__ float g_h     [(size_t)BB*SS*4*DD];
__device__ float g_ff    [(size_t)BB*SS*DD];

// ---------------- cp.async helpers -------------------------------------------
__device__ __forceinline__ void cp16(float* dst, const float* src)
{
    unsigned sa = (unsigned)__cvta_generic_to_shared(dst);
    asm volatile("cp.async.cg.shared.global [%0], [%1], 16;\n" :: "r"(sa), "l"(src));
}
__device__ __forceinline__ void cp_commit()
{
    asm volatile("cp.async.commit_group;\n");
}

// =====================================================================
// NT tf32 WMMA GEMM: C[m,n] = A[m,k] * B[n,k] (+bias[n], opt GELU)
// cp.async double-buffered, BK=32, 128x128 block, 8 warps.
// ACT: 0 = plain, 1 = +bias, 2 = +bias +exact GELU
// __launch_bounds__(256,2): cap regs at 128 -> 2 CTAs/SM.
// =====================================================================
template<int ACT>
__global__ __launch_bounds__(256, 2)
void gemm_wmma(const float* __restrict__ A, int ldA,
               const float* __restrict__ B, int ldB,
               const float* __restrict__ bias,
               float* __restrict__ C, int ldC, int K)
{
    constexpr int BM = 128, BN = 128;
    constexpr int WARPS_M = 2, WARPS_N = 4;
    constexpr int TM = BM / (WARPS_M * 16);   // 4
    constexpr int TN = BN / (WARPS_N * 16);   // 2
    constexpr int NTH = 256;
    constexpr int BK = 32;
    constexpr int APAD = 40;
    constexpr int ASTG = BM * APAD;

    extern __shared__ __align__(128) float smem[];
    float* As = smem;                 // [2][ASTG]
    float* Bs = smem + 2 * ASTG;      // [2][ASTG]

    const int tid = threadIdx.x;
    const int wid = tid >> 5;
    const int warp_m = wid % WARPS_M;
    const int warp_n = wid / WARPS_M;
    const int m0 = blockIdx.y * BM;
    const int n0 = blockIdx.x * BN;

    wmma::fragment<wmma::accumulator, 16, 16, 8, float> acc[TM][TN];
#pragma unroll
    for (int i = 0; i < TM; i++)
#pragma unroll
        for (int j = 0; j < TN; j++) wmma::fill_fragment(acc[i][j], 0.0f);

    const int nt = K / BK;

    {
#pragma unroll
        for (int i = tid; i < BM * BK / 4; i += NTH) {
            int r = i >> 3;
            int c = (i & 7) * 4;
            cp16(As + r * APAD + c, A + (size_t)(m0 + r) * ldA + c);
            cp16(Bs + r * APAD + c, B + (size_t)(n0 + r) * ldB + c);
        }
        cp_commit();
    }

    for (int it = 0; it < nt; it++) {
        const int cur = it & 1;
        if (it + 1 < nt) {
            const int k0 = (it + 1) * BK;
            float* as = As + (cur ^ 1) * ASTG;
            float* bs = Bs + (cur ^ 1) * ASTG;
#pragma unroll
            for (int i = tid; i < BM * BK / 4; i += NTH) {
                int r = i >> 3;
                int c = (i & 7) * 4;
                cp16(as + r * APAD + c, A + (size_t)(m0 + r) * ldA + k0 + c);
                cp16(bs + r * APAD + c, B + (size_t)(n0 + r) * ldB + k0 + c);
            }
            cp_commit();
            asm volatile("cp.async.wait_group 1;\n");
        } else {
            asm volatile("cp.async.wait_group 0;\n");
        }
        __syncthreads();

        const float* as = As + cur * ASTG;
        const float* bs = Bs + cur * ASTG;
#pragma unroll
        for (int ks = 0; ks < 4; ks++) {
            const int kk = ks * 8;
            wmma::fragment<wmma::matrix_a, 16, 16, 8, wmma::precision::tf32,
                           wmma::row_major> af[TM];
            wmma::fragment<wmma::matrix_b, 16, 16, 8, wmma::precision::tf32,
                           wmma::col_major> bf[TN];
#pragma unroll
            for (int i = 0; i < TM; i++)
                wmma::load_matrix_sync(af[i],
                    as + (warp_m * TM * 16 + i * 16) * APAD + kk, APAD);
#pragma unroll
            for (int j = 0; j < TN; j++)
                wmma::load_matrix_sync(bf[j],
                    bs + (warp_n * TN * 16 + j * 16) * APAD + kk, APAD);
#pragma unroll
            for (int i = 0; i < TM; i++)
#pragma unroll
                for (int j = 0; j < TN; j++)
                    wmma::mma_sync(acc[i][j], af[i], bf[j], acc[i][j]);
        }
        __syncthreads();
    }

    // ---- epilogue: stage acc in smem, write with bias/act fused ----
    constexpr int CSTR = BN + 4;      // 132 floats; 528B rows keep 16B align
    float* St = smem;                 // 128*132*4 = 67584 B < smem size
#pragma unroll
    for (int i = 0; i < TM; i++)
#pragma unroll
        for (int j = 0; j < TN; j++)
            wmma::store_matrix_sync(
                St + (warp_m * TM * 16 + i * 16) * CSTR + warp_n * TN * 16 + j * 16,
                acc[i][j], CSTR, wmma::mem_row_major);
    __syncthreads();

#pragma unroll
    for (int idx = tid; idx < BM * BN / 4; idx += NTH) {
        int r = idx >> 5;             // BN/4 == 32
        int c = (idx & 31) * 4;
        float4 v = *(float4*)&St[r * CSTR + c];
        if (ACT >= 1) {
            float4 bv = *(const float4*)&bias[n0 + c];
            v.x += bv.x; v.y += bv.y; v.z += bv.z; v.w += bv.w;
        }
        if (ACT == 2) {
            v.x = 0.5f * v.x * (1.0f + erff(v.x * 0.70710678118654752f));
            v.y = 0.5f * v.y * (1.0f + erff(v.y * 0.70710678118654752f));
            v.z = 0.5f * v.z * (1.0f + erff(v.z * 0.70710678118654752f));
            v.w = 0.5f * v.w * (1.0f + erff(v.w * 0.70710678118654752f));
        }
        *(float4*)&C[(size_t)(m0 + r) * ldC + n0 + c] = v;
    }
}

#define SMEM_NT ((2*128*40 + 2*128*40) * 4)   // 81920

// =====================================================================
// Fused flash attention (unchanged from R6)
// =====================================================================
#define FA_PAD 72
#define FA_SMEM ((128*FA_PAD + 64*FA_PAD + 64*FA_PAD + 128*FA_PAD) * 4)

template<int SQ>
__global__ __launch_bounds__(256)
void flash_attn(const float* __restrict__ qkv, float* __restrict__ attn)
{
    extern __shared__ __align__(128) float smem[];
    float* Qs = smem;
    float* Ks = Qs + 128 * FA_PAD;
    float* Vs = Ks + 64 * FA_PAD;
    float* Ss = Vs + 64 * FA_PAD;

    const int z = blockIdx.z;
    const int bb = z >> 3, hh = z & 7;
    const int q0 = blockIdx.y * 128;
    const float* Qg = qkv + (size_t)bb * SQ * 1536 + hh * 64;
    const float* Kg = Qg + 512;
    const float* Vg = Qg + 1024;

    const int tid = threadIdx.x;
    const int wid = tid >> 5;
    const int warp_m = wid & 3;
    const int warp_n = wid >> 2;

    const int row = tid >> 1;
    const int cbase = (tid & 1) * 32;

#pragma unroll
    for (int i = tid; i < 128 * 16; i += 256) {
        int r = i >> 4;
        int c = (i & 15) * 4;
        cp16(Qs + r * FA_PAD + c, Qg + (size_t)(q0 + r) * 1536 + c);
    }
    cp_commit();

    float m_run = -1e30f, l_run = 0.0f;
    float O[32];
#pragma unroll
    for (int c = 0; c < 32; c++) O[c] = 0.0f;

    const int NT = SQ / 64;
    for (int kt = 0; kt < NT; kt++) {
#pragma unroll
        for (int i = tid; i < 64 * 16; i += 256) {
            int r = i >> 4;
            int c = (i & 15) * 4;
            cp16(Ks + r * FA_PAD + c, Kg + (size_t)(kt * 64 + r) * 1536 + c);
            cp16(Vs + r * FA_PAD + c, Vg + (size_t)(kt * 64 + r) * 1536 + c);
        }
        cp_commit();
        asm volatile("cp.async.wait_group 0;\n");
        __syncthreads();

        wmma::fragment<wmma::accumulator, 16, 16, 8, float> sacc[2][2];
#pragma unroll
        for (int i = 0; i < 2; i++)
#pragma unroll
            for (int j = 0; j < 2; j++) wmma::fill_fragment(sacc[i][j], 0.0f);
#pragma unroll
        for (int ks = 0; ks < 8; ks++) {
            const int kk = ks * 8;
            wmma::fragment<wmma::matrix_a, 16, 16, 8, wmma::precision::tf32,
                           wmma::row_major> af[2];
            wmma::fragment<wmma::matrix_b, 16, 16, 8, wmma::precision::tf32,
                           wmma::col_major> bf[2];
#pragma unroll
            for (int i = 0; i < 2; i++)
                wmma::load_matrix_sync(af[i],
                    Qs + (warp_m * 32 + i * 16) * FA_PAD + kk, FA_PAD);
#pragma unroll
            for (int j = 0; j < 2; j++)
                wmma::load_matrix_sync(bf[j],
                    Ks + (warp_n * 32 + j * 16) * FA_PAD + kk, FA_PAD);
#pragma unroll
            for (int i = 0; i < 2; i++)
#pragma unroll
                for (int j = 0; j < 2; j++)
                    wmma::mma_sync(sacc[i][j], af[i], bf[j], sacc[i][j]);
        }
#pragma unroll
        for (int i = 0; i < 2; i++)
#pragma unroll
            for (int j = 0; j < 2; j++) {
#pragma unroll
                for (int t = 0; t < sacc[i][j].num_elements; t++)
                    sacc[i][j].x[t] *= 0.125f;
                wmma::store_matrix_sync(
                    Ss + (warp_m * 32 + i * 16) * FA_PAD + warp_n * 32 + j * 16,
                    sacc[i][j], FA_PAD, wmma::mem_row_major);
            }
        __syncthreads();

        float* rp = Ss + row * FA_PAD + cbase;
        float mx = -1e30f;
#pragma unroll
        for (int c = 0; c < 32; c++) mx = fmaxf(mx, rp[c]);
        mx = fmaxf(mx, __shfl_xor_sync(~0u, mx, 1));
        float m_new = fmaxf(m_run, mx);
        float alpha = __expf(m_run - m_new);
        float sum = 0.0f;
#pragma unroll
        for (int c = 0; c < 32; c++) {
            float p = __expf(rp[c] - m_new);
            rp[c] = p;
            sum += p;
        }
        sum += __shfl_xor_sync(~0u, sum, 1);
        l_run = l_run * alpha + sum;
        m_run = m_new;
        __syncthreads();

        wmma::fragment<wmma::accumulator, 16, 16, 8, float> oacc[2][2];
#pragma unroll
        for (int i = 0; i < 2; i++)
#pragma unroll
            for (int j = 0; j < 2; j++) wmma::fill_fragment(oacc[i][j], 0.0f);
#pragma unroll
        for (int ks = 0; ks < 8; ks++) {
            const int kk = ks * 8;
            wmma::fragment<wmma::matrix_a, 16, 16, 8, wmma::precision::tf32,
                           wmma::row_major> af[2];
            wmma::fragment<wmma::matrix_b, 16, 16, 8, wmma::precision::tf32,
                           wmma::row_major> bf[2];
#pragma unroll
            for (int i = 0; i < 2; i++)
                wmma::load_matrix_sync(af[i],
                    Ss + (warp_m * 32 + i * 16) * FA_PAD + kk, FA_PAD);
#pragma unroll
            for (int j = 0; j < 2; j++)
                wmma::load_matrix_sync(bf[j],
                    Vs + kk * FA_PAD + warp_n * 32 + j * 16, FA_PAD);
#pragma unroll
            for (int i = 0; i < 2; i++)
#pragma unroll
                for (int j = 0; j < 2; j++)
                    wmma::mma_sync(oacc[i][j], af[i], bf[j], oacc[i][j]);
        }
        __syncthreads();
#pragma unroll
        for (int i = 0; i < 2; i++)
#pragma unroll
            for (int j = 0; j < 2; j++)
                wmma::store_matrix_sync(
                    Ss + (warp_m * 32 + i * 16) * FA_PAD + warp_n * 32 + j * 16,
                    oacc[i][j], FA_PAD, wmma::mem_row_major);
        __syncthreads();

#pragma unroll
        for (int c = 0; c < 32; c++)
            O[c] = O[c] * alpha + rp[c];
        __syncthreads();
    }

    float inv = 1.0f / l_run;
    float* outp = attn + ((size_t)bb * SQ + q0 + row) * 512 + hh * 64 + cbase;
#pragma unroll
    for (int c4 = 0; c4 < 8; c4++) {
        float4 v;
        v.x = O[c4*4+0] * inv; v.y = O[c4*4+1] * inv;
        v.z = O[c4*4+2] * inv; v.w = O[c4*4+3] * inv;
        *(float4*)(outp + c4 * 4) = v;
    }
}

// ---------------- LN(a + b + bias) over D=512; 128 threads/row ---------------
__device__ __forceinline__ void ln_finish(float v[4], int tid, const float* g,
                                          const float* be, float* outp)
{
    float s1 = v[0] + v[1] + v[2] + v[3];
    float s2 = v[0] * v[0] + v[1] * v[1] + v[2] * v[2] + v[3] * v[3];
#pragma unroll
    for (int o = 16; o; o >>= 1) {
        s1 += __shfl_xor_sync(~0u, s1, o);
        s2 += __shfl_xor_sync(~0u, s2, o);
    }
    __shared__ float sh1[4], sh2[4];
    if ((tid & 31) == 0) { sh1[tid >> 5] = s1; sh2[tid >> 5] = s2; }
    __syncthreads();
    float rs1 = sh1[0] + sh1[1] + sh1[2] + sh1[3];
    float rs2 = sh2[0] + sh2[1] + sh2[2] + sh2[3];
    float mean = rs1 * (1.0f / 512.0f);
    float var = rs2 * (1.0f / 512.0f) - mean * mean;
    float rstd = rsqrtf(var + 1e-5f);
    float4 g4 = *(const float4*)(g + tid * 4);
    float4 b4 = *(const float4*)(be + tid * 4);
    float4 o4;
    o4.x = (v[0] - mean) * rstd * g4.x + b4.x;
    o4.y = (v[1] - mean) * rstd * g4.y + b4.y;
    o4.z = (v[2] - mean) * rstd * g4.z + b4.z;
    o4.w = (v[3] - mean) * rstd * g4.w + b4.w;
    *(float4*)outp = o4;
}

__global__ __launch_bounds__(128)
void ln_add_k(const float* __restrict__ a, const float* __restrict__ bsrc,
              const float* __restrict__ bias,
              const float* __restrict__ g, const float* __restrict__ be,
              float* __restrict__ out)
{
    const size_t base = (size_t)blockIdx.x * DD;
    const int tid = threadIdx.x;
    float4 va = *(const float4*)(a + base + tid * 4);
    float4 vb = *(const float4*)(bsrc + base + tid * 4);
    float4 vc = *(const float4*)(bias + tid * 4);
    float v[4] = {va.x + vb.x + vc.x, va.y + vb.y + vc.y,
                  va.z + vb.z + vc.z, va.w + vb.w + vc.w};
    ln_finish(v, tid, g, be, out + base + tid * 4);
}

__global__ __launch_bounds__(128)
void ln_interp_k(const float* __restrict__ x1, const float* __restrict__ a2,
                 const float* __restrict__ bias,
                 const float* __restrict__ g, const float* __restrict__ be,
                 float* __restrict__ out)
{
    const int r = blockIdx.x;
    const int b = r >> 10, i = r & 1023;
    float src = (i + 0.5f) * 0.5f - 0.5f;
    src = fminf(fmaxf(src, 0.0f), (float)(S2 - 1));
    int i0 = (int)floorf(src);
    int i1 = min(i0 + 1, S2 - 1);
    float w = src - (float)i0;

    const size_t base = (size_t)r * DD;
    const size_t b0 = ((size_t)b * S2 + i0) * DD;
    const size_t b1 = ((size_t)b * S2 + i1) * DD;
    const int tid = threadIdx.x;

    float4 vx = *(const float4*)(x1 + base + tid * 4);
    float4 v0 = *(const float4*)(a2 + b0 + tid * 4);
    float4 v1 = *(const float4*)(a2 + b1 + tid * 4);
    float4 vc = *(const float4*)(bias + tid * 4);
    float v[4];
    v[0] = vx.x + v0.x * (1.f - w) + v1.x * w + vc.x;
    v[1] = vx.y + v0.y * (1.f - w) + v1.y * w + vc.y;
    v[2] = vx.z + v0.z * (1.f - w) + v1.z * w + vc.z;
    v[3] = vx.w + v0.w * (1.f - w) + v1.w * w + vc.w;
    ln_finish(v, tid, g, be, out + base + tid * 4);
}

// avg_pool1d k=2 s=2
__global__ void pool_k(const float* __restrict__ x, float* __restrict__ out)
{
    size_t idx = (size_t)blockIdx.x * 256 + threadIdx.x;
    int d = (int)(idx & 511);
    size_t bt = idx >> 9;
    int t = (int)(bt & (S2 - 1));
    int b = (int)(bt >> 9);
    size_t src = ((size_t)b * SS + 2 * t) * DD + d;
    out[idx] = 0.5f * (x[src] + x[src + DD]);
}

// ---------------- host side ---------------------------------------------------
extern "C" void kernel_launch(void* const* d_in, const int* in_sizes, int n_in,
                              void* d_out, int out_size)
{
    const float* x      = (const float*)d_in[0];
    const float* w_in1  = (const float*)d_in[1];
    const float* b_in1  = (const float*)d_in[2];
    const float* w_out1 = (const float*)d_in[3];
    const float* b_out1 = (const float*)d_in[4];
    const float* w_in2  = (const float*)d_in[5];
    const float* b_in2  = (const float*)d_in[6];
    const float* w_out2 = (const float*)d_in[7];
    const float* b_out2 = (const float*)d_in[8];
    const float* g1     = (const float*)d_in[9];
    const float* beta1  = (const float*)d_in[10];
    const float* g2     = (const float*)d_in[11];
    const float* beta2  = (const float*)d_in[12];
    const float* g3     = (const float*)d_in[13];
    const float* beta3  = (const float*)d_in[14];
    const float* w_ff1  = (const float*)d_in[15];
    const float* b_ff1  = (const float*)d_in[16];
    const float* w_ff2  = (const float*)d_in[17];
    const float* b_ff2  = (const float*)d_in[18];

    float *qkv, *attn, *x1, *pooled, *a2, *x2, *h, *ff;
    cudaGetSymbolAddress((void**)&qkv,    g_qkv);
    cudaGetSymbolAddress((void**)&attn,   g_attn);
    cudaGetSymbolAddress((void**)&x1,     g_x1);
    cudaGetSymbolAddress((void**)&pooled, g_pooled);
    cudaGetSymbolAddress((void**)&a2,     g_a2);
    cudaGetSymbolAddress((void**)&x2,     g_x2);
    cudaGetSymbolAddress((void**)&h,      g_h);
    cudaGetSymbolAddress((void**)&ff,     g_ff);

    cudaFuncSetAttribute(gemm_wmma<0>,
                         cudaFuncAttributeMaxDynamicSharedMemorySize, SMEM_NT);
    cudaFuncSetAttribute(gemm_wmma<1>,
                         cudaFuncAttributeMaxDynamicSharedMemorySize, SMEM_NT);
    cudaFuncSetAttribute(gemm_wmma<2>,
                         cudaFuncAttributeMaxDynamicSharedMemorySize, SMEM_NT);
    cudaFuncSetAttribute(flash_attn<SS>,
                         cudaFuncAttributeMaxDynamicSharedMemorySize, FA_SMEM);
    cudaFuncSetAttribute(flash_attn<S2>,
                         cudaFuncAttributeMaxDynamicSharedMemorySize, FA_SMEM);

    const int M1 = BB * SS;   // 8192
    const int M2 = BB * S2;   // 4096

    // ---- MHA 1 ----
    gemm_wmma<1><<<dim3(1536/128, M1/128), 256, SMEM_NT>>>(
        x, 512, w_in1, 512, b_in1, qkv, 1536, 512);
    flash_attn<SS><<<dim3(1, SS/128, BB*HH), 256, FA_SMEM>>>(qkv, attn);
    gemm_wmma<0><<<dim3(512/128, M1/128), 256, SMEM_NT>>>(
        attn, 512, w_out1, 512, nullptr, ff, 512, 512);
    ln_add_k<<<M1, 128>>>(x, ff, b_out1, g1, beta1, x1);

    // ---- pool + MHA 2 ----
    pool_k<<<(BB*S2*DD)/256, 256>>>(x1, pooled);
    gemm_wmma<1><<<dim3(1536/128, M2/128), 256, SMEM_NT>>>(
        pooled, 512, w_in2, 512, b_in2, qkv, 1536, 512);
    flash_attn<S2><<<dim3(1, S2/128, BB*HH), 256, FA_SMEM>>>(qkv, attn);
    gemm_wmma<0><<<dim3(512/128, M2/128), 256, SMEM_NT>>>(
        attn, 512, w_out2, 512, nullptr, a2, 512, 512);

    // ---- upsample + residual + LN2 ----
    ln_interp_k<<<M1, 128>>>(x1, a2, b_out2, g2, beta2, x2);

    // ---- FFN ----
    gemm_wmma<2><<<dim3(2048/128, M1/128), 256, SMEM_NT>>>(
        x2, 512, w_ff1, 512, b_ff1, h, 2048, 512);
    gemm_wmma<0><<<dim3(512/128, M1/128), 256, SMEM_NT>>>(
        h, 2048, w_ff2, 2048, nullptr, ff, 512, 2048);
    ln_add_k<<<M1, 128>>>(x2, ff, b_ff2, g3, beta3, (float*)d_out);
}